// round 8
// baseline (speedup 1.0000x reference)
#include <cuda_runtime.h>
#include <cuda_bf16.h>
#include <cstdint>
#include <math.h>

#define L_SEQ 2048
#define E_DIM 2048
#define H_NUM 16
#define D_HEAD 128
#define E3 6144

// ---------------------------------------------------------------------------
// Device-global scratch (allocation-free rule)
// ---------------------------------------------------------------------------
__device__ __align__(16) __nv_bfloat16 g_xh[L_SEQ * E_DIM];
__device__ __align__(16) __nv_bfloat16 g_xl[L_SEQ * E_DIM];
__device__ __align__(16) __nv_bfloat16 g_wih[E3 * E_DIM];
__device__ __align__(16) __nv_bfloat16 g_wil[E3 * E_DIM];
__device__ __align__(16) __nv_bfloat16 g_woh[E_DIM * E_DIM];
__device__ __align__(16) __nv_bfloat16 g_wol[E_DIM * E_DIM];
__device__ __align__(16) __nv_bfloat16 g_qkvh[L_SEQ * E3];
__device__ __align__(16) __nv_bfloat16 g_qkvl[L_SEQ * E3];
__device__ __align__(16) __nv_bfloat16 g_ch[L_SEQ * E_DIM];
__device__ __align__(16) __nv_bfloat16 g_cl[L_SEQ * E_DIM];

__device__ __forceinline__ uint32_t smem_u32(const void* p) {
    uint32_t a;
    asm("{ .reg .u64 t; cvta.to.shared.u64 t, %1; cvt.u32.u64 %0, t; }" : "=r"(a) : "l"(p));
    return a;
}
__device__ __forceinline__ void cp_async16(uint32_t dst, const void* src) {
    asm volatile("cp.async.cg.shared.global [%0], [%1], 16;" :: "r"(dst), "l"(src));
}
__device__ __forceinline__ void cp_commit() {
    asm volatile("cp.async.commit_group;" ::: "memory");
}
__device__ __forceinline__ void cp_wait2() {
    asm volatile("cp.async.wait_group 2;" ::: "memory");
}
__device__ __forceinline__ void cp_wait1() {
    asm volatile("cp.async.wait_group 1;" ::: "memory");
}
__device__ __forceinline__ void cp_wait0() {
    asm volatile("cp.async.wait_group 0;" ::: "memory");
}
__device__ __forceinline__ void ldm_x4(uint32_t* r, uint32_t addr) {
    asm volatile("ldmatrix.sync.aligned.m8n8.x4.shared.b16 {%0,%1,%2,%3}, [%4];"
                 : "=r"(r[0]), "=r"(r[1]), "=r"(r[2]), "=r"(r[3]) : "r"(addr));
}
__device__ __forceinline__ void ldm_x4_t(uint32_t* r, uint32_t addr) {
    asm volatile("ldmatrix.sync.aligned.m8n8.x4.trans.shared.b16 {%0,%1,%2,%3}, [%4];"
                 : "=r"(r[0]), "=r"(r[1]), "=r"(r[2]), "=r"(r[3]) : "r"(addr));
}
__device__ __forceinline__ void mma_bf16(float* c, const uint32_t* a, const uint32_t* b) {
    asm("mma.sync.aligned.m16n8k16.row.col.f32.bf16.bf16.f32 "
        "{%0,%1,%2,%3}, {%4,%5,%6,%7}, {%8,%9}, {%0,%1,%2,%3};"
        : "+f"(c[0]), "+f"(c[1]), "+f"(c[2]), "+f"(c[3])
        : "r"(a[0]), "r"(a[1]), "r"(a[2]), "r"(a[3]), "r"(b[0]), "r"(b[1]));
}
__device__ __forceinline__ uint32_t pack_bf2(__nv_bfloat16 a, __nv_bfloat16 b) {
    __nv_bfloat162 t(a, b);
    return *reinterpret_cast<uint32_t*>(&t);
}
// exp2 polynomial (degree-6, rel err <= ~3e-5), FMA-pipe only
__device__ __forceinline__ float exp2p(float t) {
    t = fmaxf(t, -126.f);
    float fl = floorf(t);
    float f = t - fl;
    float p = 1.5403530e-4f;
    p = fmaf(p, f, 1.3333558e-3f);
    p = fmaf(p, f, 9.6181291e-3f);
    p = fmaf(p, f, 5.5504109e-2f);
    p = fmaf(p, f, 2.4022651e-1f);
    p = fmaf(p, f, 6.9314718e-1f);
    p = fmaf(p, f, 1.0f);
    return p * __int_as_float(((int)fl + 127) << 23);
}

// ---------------------------------------------------------------------------
// fp32 -> split bf16 (hi + lo)
// ---------------------------------------------------------------------------
__global__ void split_bf16_kernel(const float* __restrict__ in,
                                  __nv_bfloat16* __restrict__ hi,
                                  __nv_bfloat16* __restrict__ lo, int n4)
{
    int i = blockIdx.x * blockDim.x + threadIdx.x;
    if (i >= n4) return;
    float4 v = ((const float4*)in)[i];
    __nv_bfloat16 hx = __float2bfloat16(v.x);
    __nv_bfloat16 hy = __float2bfloat16(v.y);
    __nv_bfloat16 hz = __float2bfloat16(v.z);
    __nv_bfloat16 hw = __float2bfloat16(v.w);
    __nv_bfloat16 lx = __float2bfloat16(v.x - __bfloat162float(hx));
    __nv_bfloat16 ly = __float2bfloat16(v.y - __bfloat162float(hy));
    __nv_bfloat16 lz = __float2bfloat16(v.z - __bfloat162float(hz));
    __nv_bfloat16 lw = __float2bfloat16(v.w - __bfloat162float(hw));
    ((__nv_bfloat162*)hi)[2 * i]     = __nv_bfloat162(hx, hy);
    ((__nv_bfloat162*)hi)[2 * i + 1] = __nv_bfloat162(hz, hw);
    ((__nv_bfloat162*)lo)[2 * i]     = __nv_bfloat162(lx, ly);
    ((__nv_bfloat162*)lo)[2 * i + 1] = __nv_bfloat162(lz, lw);
}

// ---------------------------------------------------------------------------
// Split-bf16 mma.sync GEMM: C = A @ B^T + bias.
// CTA tile 128(M) x 256(N), 8 warps of 64x64, K-chunk 32, 4-stage ring.
// Halves smem bytes per MMA vs 128x128 (the R7 smem-BW binder).
// ---------------------------------------------------------------------------
#define GM_A_BYTES 8192                    // 128 rows x 64 B (h or l)
#define GM_B_BYTES 16384                   // 256 rows x 64 B (h or l)
#define GM_STAGE (2 * GM_A_BYTES + 2 * GM_B_BYTES)  // 48 KB
#define GM_NSTAGE 4
#define GM_SMEM (GM_NSTAGE * GM_STAGE)     // 192 KB

__device__ __forceinline__ void issue_tile_rows(uint32_t smem_tile,
                                                const __nv_bfloat16* __restrict__ G,
                                                int row0, int k0, int K, int tid,
                                                int iters /* nrows*4/256 */)
{
    for (int t = 0; t < iters; t++) {
        int id = tid + t * 256;
        int r  = id >> 2;
        int c  = id & 3;
        int pc = c ^ ((r >> 1) & 3);
        cp_async16(smem_tile + r * 64 + pc * 16,
                   G + (size_t)(row0 + r) * K + k0 + c * 8);
    }
}
__device__ __forceinline__ void issue_stage(uint32_t base,
                                            const __nv_bfloat16* Ah, const __nv_bfloat16* Al,
                                            const __nv_bfloat16* Bh, const __nv_bfloat16* Bl,
                                            int m0, int n0, int k0, int K, int tid)
{
    issue_tile_rows(base,                             Ah, m0, k0, K, tid, 2);
    issue_tile_rows(base + GM_A_BYTES,                Al, m0, k0, K, tid, 2);
    issue_tile_rows(base + 2 * GM_A_BYTES,            Bh, n0, k0, K, tid, 4);
    issue_tile_rows(base + 2 * GM_A_BYTES + GM_B_BYTES, Bl, n0, k0, K, tid, 4);
}

__global__ __launch_bounds__(256, 1) void gemm_mma(
    const __nv_bfloat16* __restrict__ Ah, const __nv_bfloat16* __restrict__ Al,
    const __nv_bfloat16* __restrict__ Bh, const __nv_bfloat16* __restrict__ Bl,
    const float* __restrict__ bias, float* __restrict__ Cf,
    __nv_bfloat16* __restrict__ Ch, __nv_bfloat16* __restrict__ Cl,
    int M, int N, int K)
{
    extern __shared__ char smc[];
    const uint32_t sb = smem_u32(smc);
    const int tid = threadIdx.x;
    const int lane = tid & 31;
    const int wid = tid >> 5;
    const int wm = wid & 1;            // 2 blocks of 64 rows
    const int wn = wid >> 1;           // 4 blocks of 64 cols
    const int m0 = blockIdx.y * 128;
    const int n0 = blockIdx.x * 256;

    const int S = K >> 5;

    // prologue: stages 0..2
#pragma unroll
    for (int s = 0; s < 3; s++) {
        issue_stage(sb + s * GM_STAGE, Ah, Al, Bh, Bl, m0, n0, s * 32, K, tid);
        cp_commit();
    }

    float acc[4][8][4];
#pragma unroll
    for (int i = 0; i < 4; i++)
#pragma unroll
        for (int j = 0; j < 8; j++)
#pragma unroll
            for (int r = 0; r < 4; r++) acc[i][j][r] = 0.f;

    const int a_r = wm * 64 + (lane & 15);
    const int a_c = (lane >> 4);
    const int s_br = (lane & 7) + ((lane >> 4) & 1) * 8;
    const int s_bc = (lane >> 3) & 1;

    for (int s = 0; s < S; s++) {
        cp_wait2();               // stage s resident; s+1, s+2 in flight
        __syncthreads();          // buffer (s+3)&3 free

        if (s + 3 < S)
            issue_stage(sb + ((s + 3) & 3) * GM_STAGE, Ah, Al, Bh, Bl,
                        m0, n0, (s + 3) * 32, K, tid);
        cp_commit();

        const uint32_t base = sb + (s & 3) * GM_STAGE;
        const uint32_t tAh = base;
        const uint32_t tAl = base + GM_A_BYTES;
        const uint32_t tBh = base + 2 * GM_A_BYTES;
        const uint32_t tBl = base + 2 * GM_A_BYTES + GM_B_BYTES;

#pragma unroll
        for (int ks = 0; ks < 2; ks++) {
            uint32_t ah[4][4], al[4][4];
#pragma unroll
            for (int mt = 0; mt < 4; mt++) {
                int r = a_r + mt * 16;
                int pc = (ks * 2 + a_c) ^ ((r >> 1) & 3);
                uint32_t off = r * 64 + pc * 16;
                ldm_x4(ah[mt], tAh + off);
                ldm_x4(al[mt], tAl + off);
            }
            // B: 4 LDSM.x4 groups per h/l -> 8 n-tiles; interleave per group
#pragma unroll
            for (int g = 0; g < 4; g++) {
                int r = wn * 64 + g * 16 + s_br;
                int pc = (ks * 2 + s_bc) ^ ((r >> 1) & 3);
                uint32_t off = r * 64 + pc * 16;
                uint32_t th[4], tl[4];
                ldm_x4(th, tBh + off);
                ldm_x4(tl, tBl + off);
                uint32_t bh0[2] = {th[0], th[1]}, bh1[2] = {th[2], th[3]};
                uint32_t bl0[2] = {tl[0], tl[1]}, bl1[2] = {tl[2], tl[3]};
                float* a0 = acc[0][2 * g];     float* a1 = acc[0][2 * g + 1];
                // pass 1: ah*bh for 4 m-tiles x 2 n-tiles
#pragma unroll
                for (int mt = 0; mt < 4; mt++) {
                    mma_bf16(acc[mt][2 * g],     ah[mt], bh0);
                    mma_bf16(acc[mt][2 * g + 1], ah[mt], bh1);
                }
                // pass 2: al*bh
#pragma unroll
                for (int mt = 0; mt < 4; mt++) {
                    mma_bf16(acc[mt][2 * g],     al[mt], bh0);
                    mma_bf16(acc[mt][2 * g + 1], al[mt], bh1);
                }
                // pass 3: ah*bl
#pragma unroll
                for (int mt = 0; mt < 4; mt++) {
                    mma_bf16(acc[mt][2 * g],     ah[mt], bl0);
                    mma_bf16(acc[mt][2 * g + 1], ah[mt], bl1);
                }
                (void)a0; (void)a1;
            }
        }
    }

    const int cm = m0 + wm * 64 + (lane >> 2);
    const int cn = n0 + wn * 64 + (lane & 3) * 2;
    if (Cf) {
#pragma unroll
        for (int nt = 0; nt < 8; nt++) {
            float b0 = bias[cn + nt * 8];
            float b1 = bias[cn + nt * 8 + 1];
#pragma unroll
            for (int mt = 0; mt < 4; mt++) {
                float* r0 = Cf + (size_t)(cm + mt * 16) * N + cn + nt * 8;
                float* r1 = r0 + 8 * N;
                *(float2*)r0 = make_float2(acc[mt][nt][0] + b0, acc[mt][nt][1] + b1);
                *(float2*)r1 = make_float2(acc[mt][nt][2] + b0, acc[mt][nt][3] + b1);
            }
        }
    } else {
#pragma unroll
        for (int nt = 0; nt < 8; nt++) {
            float b0 = bias[cn + nt * 8];
            float b1 = bias[cn + nt * 8 + 1];
#pragma unroll
            for (int mt = 0; mt < 4; mt++) {
#pragma unroll
                for (int half = 0; half < 2; half++) {
                    float v0 = acc[mt][nt][2 * half + 0] + b0;
                    float v1 = acc[mt][nt][2 * half + 1] + b1;
                    __nv_bfloat16 h0 = __float2bfloat16(v0);
                    __nv_bfloat16 h1 = __float2bfloat16(v1);
                    __nv_bfloat16 l0 = __float2bfloat16(v0 - __bfloat162float(h0));
                    __nv_bfloat16 l1 = __float2bfloat16(v1 - __bfloat162float(h1));
                    size_t off = (size_t)(cm + mt * 16 + half * 8) * N + cn + nt * 8;
                    *(uint32_t*)(Ch + off) = pack_bf2(h0, h1);
                    *(uint32_t*)(Cl + off) = pack_bf2(l0, l1);
                }
            }
        }
    }
}

// ---------------------------------------------------------------------------
// Tensor-core flash attention (unchanged from R7 passing kernel)
// ---------------------------------------------------------------------------
#define ATT_STAGE 65536
#define ATT_SMEM (2 * ATT_STAGE)
#define ATT_NT 32

__device__ __forceinline__ uint32_t sw_addr(uint32_t base, int r, int c) {
    return base + r * 256 + ((c ^ (r & 7)) << 4);
}
__device__ __forceinline__ void att_load_tile(uint32_t dst,
                                              const __nv_bfloat16* __restrict__ g,
                                              int k0, int tid)
{
#pragma unroll
    for (int i = 0; i < 4; i++) {
        int id = tid + i * 256;
        int r = id >> 4;
        int c = id & 15;
        cp_async16(sw_addr(dst, r, c), g + (size_t)(k0 + r) * E3 + c * 8);
    }
}

__global__ __launch_bounds__(256, 1) void attn_tc(
    const __nv_bfloat16* __restrict__ qkvh, const __nv_bfloat16* __restrict__ qkvl,
    const float* __restrict__ biasM,
    __nv_bfloat16* __restrict__ ch, __nv_bfloat16* __restrict__ cl)
{
    extern __shared__ char smc[];
    const uint32_t sb = smem_u32(smc);
    const int tid = threadIdx.x;
    const int lane = tid & 31;
    const int wid = tid >> 5;
    const int h = blockIdx.y;
    const int q0 = blockIdx.x * 128;

    const uint32_t buf0 = sb;
    const uint32_t buf1 = sb + ATT_STAGE;

    const __nv_bfloat16* gKh = qkvh + E_DIM + h * D_HEAD;
    const __nv_bfloat16* gKl = qkvl + E_DIM + h * D_HEAD;
    const __nv_bfloat16* gVh = qkvh + 2 * E_DIM + h * D_HEAD;
    const __nv_bfloat16* gVl = qkvl + 2 * E_DIM + h * D_HEAD;

    {
        const __nv_bfloat16* gqh = qkvh + (size_t)q0 * E3 + h * D_HEAD;
        const __nv_bfloat16* gql = qkvl + (size_t)q0 * E3 + h * D_HEAD;
#pragma unroll
        for (int i = 0; i < 8; i++) {
            int id = tid + i * 256;
            int r = id >> 4;
            int c = id & 15;
            cp_async16(sw_addr(buf0, r, c), gqh + (size_t)r * E3 + c * 8);
        }
#pragma unroll
        for (int i = 0; i < 8; i++) {
            int id = tid + i * 256;
            int r = id >> 4;
            int c = id & 15;
            cp_async16(sw_addr(buf0 + 32768, r, c), gql + (size_t)r * E3 + c * 8);
        }
        cp_commit();
    }
    att_load_tile(buf1 + 0,     gKh, 0, tid);
    att_load_tile(buf1 + 16384, gKl, 0, tid);
    att_load_tile(buf1 + 32768, gVh, 0, tid);
    att_load_tile(buf1 + 49152, gVl, 0, tid);
    cp_commit();

    cp_wait1();
    __syncthreads();

    uint32_t qh_f[8][4], ql_f[8][4];
    {
        int r = wid * 16 + (lane & 15);
#pragma unroll
        for (int kf = 0; kf < 8; kf++) {
            int c = 2 * kf + (lane >> 4);
            ldm_x4(qh_f[kf], sw_addr(buf0, r, c));
            ldm_x4(ql_f[kf], sw_addr(buf0 + 32768, r, c));
        }
    }
    __syncthreads();

    att_load_tile(buf0 + 0,     gKh, 64, tid);
    att_load_tile(buf0 + 16384, gKl, 64, tid);
    att_load_tile(buf0 + 32768, gVh, 64, tid);
    att_load_tile(buf0 + 49152, gVl, 64, tid);
    cp_commit();

    float mA = -INFINITY, mB = -INFINITY, lA = 0.f, lB = 0.f;
    float ctx[16][4];
#pragma unroll
    for (int i = 0; i < 16; i++)
#pragma unroll
        for (int j = 0; j < 4; j++) ctx[i][j] = 0.f;

    const float SCALE = 0.088388347648318447f;
    const float LOG2E = 1.4426950408889634f;
    const int rA = q0 + wid * 16 + (lane >> 2);
    const int rB = rA + 8;
    const int cb = 2 * (lane & 3);

    const int s_br = (lane & 7) + ((lane >> 4) & 1) * 8;
    const int s_bc = (lane >> 3) & 1;
    const int a_r = (lane & 15);
    const int a_c = (lane >> 4);

    for (int kt = 0; kt < ATT_NT; kt++) {
        if (kt < ATT_NT - 2) cp_wait1(); else cp_wait0();
        __syncthreads();
        const uint32_t buf = (kt & 1) ? buf0 : buf1;
        const int k0 = kt * 64;

        float sacc[8][4];
#pragma unroll
        for (int i = 0; i < 8; i++)
#pragma unroll
            for (int j = 0; j < 4; j++) sacc[i][j] = 0.f;

#pragma unroll
        for (int kf = 0; kf < 8; kf++) {
#pragma unroll
            for (int ng = 0; ng < 4; ng++) {
                int r = ng * 16 + s_br;
                int c = 2 * kf + s_bc;
                uint32_t th[4], tl[4];
                ldm_x4(th, sw_addr(buf + 0, r, c));
                ldm_x4(tl, sw_addr(buf + 16384, r, c));
                uint32_t bh0[2] = {th[0], th[1]}, bh1[2] = {th[2], th[3]};
                uint32_t bl0[2] = {tl[0], tl[1]}, bl1[2] = {tl[2], tl[3]};
                mma_bf16(sacc[2 * ng],     qh_f[kf], bh0);
                mma_bf16(sacc[2 * ng + 1], qh_f[kf], bh1);
                mma_bf16(sacc[2 * ng],     ql_f[kf], bh0);
                mma_bf16(sacc[2 * ng + 1], ql_f[kf], bh1);
                mma_bf16(sacc[2 * ng],     qh_f[kf], bl0);
                mma_bf16(sacc[2 * ng + 1], qh_f[kf], bl1);
            }
        }

        float mxA = -INFINITY, mxB = -INFINITY;
#pragma unroll
        for (int nt = 0; nt < 8; nt++) {
            float2 bA = *(const float2*)(biasM + (size_t)rA * L_SEQ + k0 + nt * 8 + cb);
            float2 bB = *(const float2*)(biasM + (size_t)rB * L_SEQ + k0 + nt * 8 + cb);
            sacc[nt][0] = fmaf(sacc[nt][0], SCALE, bA.x);
            sacc[nt][1] = fmaf(sacc[nt][1], SCALE, bA.y);
            sacc[nt][2] = fmaf(sacc[nt][2], SCALE, bB.x);
            sacc[nt][3] = fmaf(sacc[nt][3], SCALE, bB.y);
            mxA = fmaxf(mxA, fmaxf(sacc[nt][0], sacc[nt][1]));
            mxB = fmaxf(mxB, fmaxf(sacc[nt][2], sacc[nt][3]));
        }
        mxA = fmaxf(mxA, __shfl_xor_sync(0xffffffffu, mxA, 1));
        mxA = fmaxf(mxA, __shfl_xor_sync(0xffffffffu, mxA, 2));
        mxB = fmaxf(mxB, __shfl_xor_sync(0xffffffffu, mxB, 1));
        mxB = fmaxf(mxB, __shfl_xor_sync(0xffffffffu, mxB, 2));
        float mnA = fmaxf(mA, mxA), mnB = fmaxf(mB, mxB);
        float alA = exp2p((mA - mnA) * LOG2E);
        float alB = exp2p((mB - mnB) * LOG2E);
        float negA = mnA * LOG2E, negB = mnB * LOG2E;
        float sumA = 0.f, sumB = 0.f;
#pragma unroll
        for (int nt = 0; nt < 8; nt++) {
            sacc[nt][0] = exp2p(fmaf(sacc[nt][0], LOG2E, -negA));
            sacc[nt][1] = exp2p(fmaf(sacc[nt][1], LOG2E, -negA));
            sacc[nt][2] = exp2p(fmaf(sacc[nt][2], LOG2E, -negB));
            sacc[nt][3] = exp2p(fmaf(sacc[nt][3], LOG2E, -negB));
            sumA += sacc[nt][0] + sacc[nt][1];
            sumB += sacc[nt][2] + sacc[nt][3];
        }
        sumA += __shfl_xor_sync(0xffffffffu, sumA, 1);
        sumA += __shfl_xor_sync(0xffffffffu, sumA, 2);
        sumB += __shfl_xor_sync(0xffffffffu, sumB, 1);
        sumB += __shfl_xor_sync(0xffffffffu, sumB, 2);
        lA = lA * alA + sumA;
        lB = lB * alB + sumB;
        mA = mnA; mB = mnB;
#pragma unroll
        for (int nt = 0; nt < 16; nt++) {
            ctx[nt][0] *= alA; ctx[nt][1] *= alA;
            ctx[nt][2] *= alB; ctx[nt][3] *= alB;
        }

        uint32_t pah[4][4], pal[4][4];
#pragma unroll
        for (int kb = 0; kb < 4; kb++) {
#pragma unroll
            for (int half = 0; half < 2; half++) {
#pragma unroll
                for (int sub = 0; sub < 2; sub++) {
                    float p0 = sacc[2 * kb + sub][2 * half + 0];
                    float p1 = sacc[2 * kb + sub][2 * half + 1];
                    __nv_bfloat16 h0 = __float2bfloat16(p0);
                    __nv_bfloat16 h1 = __float2bfloat16(p1);
                    __nv_bfloat16 l0 = __float2bfloat16(p0 - __bfloat162float(h0));
                    __nv_bfloat16 l1 = __float2bfloat16(p1 - __bfloat162float(h1));
                    pah[kb][sub * 2 + half] = pack_bf2(h0, h1);
                    pal[kb][sub * 2 + half] = pack_bf2(l0, l1);
                }
            }
        }

#pragma unroll
        for (int kb = 0; kb < 4; kb++) {
#pragma unroll
            for (int db = 0; db < 8; db++) {
                int r = kb * 16 + a_r;
                int c = 2 * db + a_c;
                uint32_t th[4], tl[4];
                ldm_x4_t(th, sw_addr(buf + 32768, r, c));
                ldm_x4_t(tl, sw_addr(buf + 49152, r, c));
                uint32_t bh0[2] = {th[0], th[1]}, bh1[2] = {th[2], th[3]};
                uint32_t bl0[2] = {tl[0], tl[1]}, bl1[2] = {tl[2], tl[3]};
                mma_bf16(ctx[2 * db],     pah[kb], bh0);
                mma_bf16(ctx[2 * db + 1], pah[kb], bh1);
                mma_bf16(ctx[2 * db],     pal[kb], bh0);
                mma_bf16(ctx[2 * db + 1], pal[kb], bh1);
                mma_bf16(ctx[2 * db],     pah[kb], bl0);
                mma_bf16(ctx[2 * db + 1], pah[kb], bl1);
            }
        }

        __syncthreads();
        if (kt + 2 < ATT_NT) {
            const uint32_t nbuf = (kt & 1) ? buf0 : buf1;
            const int nk0 = (kt + 2) * 64;
            att_load_tile(nbuf + 0,     gKh, nk0, tid);
            att_load_tile(nbuf + 16384, gKl, nk0, tid);
            att_load_tile(nbuf + 32768, gVh, nk0, tid);
            att_load_tile(nbuf + 49152, gVl, nk0, tid);
            cp_commit();
        }
    }

    float iA = 1.f / lA, iB = 1.f / lB;
#pragma unroll
    for (int nt = 0; nt < 16; nt++) {
        int col = h * D_HEAD + nt * 8 + cb;
        float v0 = ctx[nt][0] * iA, v1 = ctx[nt][1] * iA;
        float v2 = ctx[nt][2] * iB, v3 = ctx[nt][3] * iB;
        __nv_bfloat16 h0 = __float2bfloat16(v0), h1 = __float2bfloat16(v1);
        __nv_bfloat16 h2 = __float2bfloat16(v2), h3 = __float2bfloat16(v3);
        __nv_bfloat16 l0 = __float2bfloat16(v0 - __bfloat162float(h0));
        __nv_bfloat16 l1 = __float2bfloat16(v1 - __bfloat162float(h1));
        __nv_bfloat16 l2 = __float2bfloat16(v2 - __bfloat162float(h2));
        __nv_bfloat16 l3 = __float2bfloat16(v3 - __bfloat162float(h3));
        *(uint32_t*)(ch + (size_t)rA * E_DIM + col) = pack_bf2(h0, h1);
        *(uint32_t*)(cl + (size_t)rA * E_DIM + col) = pack_bf2(l0, l1);
        *(uint32_t*)(ch + (size_t)rB * E_DIM + col) = pack_bf2(h2, h3);
        *(uint32_t*)(cl + (size_t)rB * E_DIM + col) = pack_bf2(l2, l3);
    }
}

// ---------------------------------------------------------------------------
extern "C" void kernel_launch(void* const* d_in, const int* in_sizes, int n_in,
                              void* d_out, int out_size)
{
    const float* x     = (const float*)d_in[0];
    const float* biasM = (const float*)d_in[1];
    const float* w_in  = (const float*)d_in[2];
    const float* b_in  = (const float*)d_in[3];
    const float* w_out = (const float*)d_in[4];
    const float* b_out = (const float*)d_in[5];
    float* out = (float*)d_out;

    __nv_bfloat16 *xh, *xl, *wih, *wil, *woh, *wol, *qkvh, *qkvl, *ch, *cl;
    cudaGetSymbolAddress((void**)&xh, g_xh);
    cudaGetSymbolAddress((void**)&xl, g_xl);
    cudaGetSymbolAddress((void**)&wih, g_wih);
    cudaGetSymbolAddress((void**)&wil, g_wil);
    cudaGetSymbolAddress((void**)&woh, g_woh);
    cudaGetSymbolAddress((void**)&wol, g_wol);
    cudaGetSymbolAddress((void**)&qkvh, g_qkvh);
    cudaGetSymbolAddress((void**)&qkvl, g_qkvl);
    cudaGetSymbolAddress((void**)&ch, g_ch);
    cudaGetSymbolAddress((void**)&cl, g_cl);

    cudaFuncSetAttribute(gemm_mma, cudaFuncAttributeMaxDynamicSharedMemorySize, GM_SMEM);
    cudaFuncSetAttribute(attn_tc, cudaFuncAttributeMaxDynamicSharedMemorySize, ATT_SMEM);

    {
        int n4 = (L_SEQ * E_DIM) / 4;
        split_bf16_kernel<<<(n4 + 255) / 256, 256>>>(x, xh, xl, n4);
        int w4 = (E3 * E_DIM) / 4;
        split_bf16_kernel<<<(w4 + 255) / 256, 256>>>(w_in, wih, wil, w4);
        int o4 = (E_DIM * E_DIM) / 4;
        split_bf16_kernel<<<(o4 + 255) / 256, 256>>>(w_out, woh, wol, o4);
    }

    // 1) QKV projection -> split bf16 output   [2048, 6144]
    gemm_mma<<<dim3(E3 / 256, L_SEQ / 128), 256, GM_SMEM>>>(
        xh, xl, wih, wil, b_in, nullptr, qkvh, qkvl, L_SEQ, E3, E_DIM);

    // 2) Tensor-core attention -> split bf16 ctx
    attn_tc<<<dim3(L_SEQ / 128, H_NUM), 256, ATT_SMEM>>>(
        qkvh, qkvl, biasM, ch, cl);

    // 3) out projection -> fp32 output   [2048, 2048]
    gemm_mma<<<dim3(E_DIM / 256, L_SEQ / 128), 256, GM_SMEM>>>(
        ch, cl, woh, wol, b_out, out, nullptr, nullptr, L_SEQ, E_DIM, E_DIM);
}

// round 9
// speedup vs baseline: 1.3500x; 1.3500x over previous
#include <cuda_runtime.h>
#include <cuda_fp16.h>
#include <cstdint>
#include <math.h>

#define L_SEQ 2048
#define E_DIM 2048
#define H_NUM 16
#define D_HEAD 128
#define E3 6144

// ---------------------------------------------------------------------------
// Device-global scratch (allocation-free rule)
// ---------------------------------------------------------------------------
__device__ __align__(16) __half g_xh[L_SEQ * E_DIM];
__device__ __align__(16) __half g_xl[L_SEQ * E_DIM];
__device__ __align__(16) __half g_wih[E3 * E_DIM];
__device__ __align__(16) __half g_woh[E_DIM * E_DIM];
__device__ __align__(16) __half g_qkvh[L_SEQ * E3];
__device__ __align__(16) __half g_qkvl[L_SEQ * E3];
__device__ __align__(16) __half g_ch[L_SEQ * E_DIM];
__device__ __align__(16) __half g_cl[L_SEQ * E_DIM];

__device__ __forceinline__ uint32_t smem_u32(const void* p) {
    uint32_t a;
    asm("{ .reg .u64 t; cvta.to.shared.u64 t, %1; cvt.u32.u64 %0, t; }" : "=r"(a) : "l"(p));
    return a;
}
__device__ __forceinline__ void cp_async16(uint32_t dst, const void* src) {
    asm volatile("cp.async.cg.shared.global [%0], [%1], 16;" :: "r"(dst), "l"(src));
}
__device__ __forceinline__ void cp_commit() {
    asm volatile("cp.async.commit_group;" ::: "memory");
}
__device__ __forceinline__ void cp_wait2() {
    asm volatile("cp.async.wait_group 2;" ::: "memory");
}
__device__ __forceinline__ void cp_wait1() {
    asm volatile("cp.async.wait_group 1;" ::: "memory");
}
__device__ __forceinline__ void cp_wait0() {
    asm volatile("cp.async.wait_group 0;" ::: "memory");
}
__device__ __forceinline__ void ldm_x4(uint32_t* r, uint32_t addr) {
    asm volatile("ldmatrix.sync.aligned.m8n8.x4.shared.b16 {%0,%1,%2,%3}, [%4];"
                 : "=r"(r[0]), "=r"(r[1]), "=r"(r[2]), "=r"(r[3]) : "r"(addr));
}
__device__ __forceinline__ void ldm_x4_t(uint32_t* r, uint32_t addr) {
    asm volatile("ldmatrix.sync.aligned.m8n8.x4.trans.shared.b16 {%0,%1,%2,%3}, [%4];"
                 : "=r"(r[0]), "=r"(r[1]), "=r"(r[2]), "=r"(r[3]) : "r"(addr));
}
__device__ __forceinline__ void mma_f16(float* c, const uint32_t* a, const uint32_t* b) {
    asm("mma.sync.aligned.m16n8k16.row.col.f32.f16.f16.f32 "
        "{%0,%1,%2,%3}, {%4,%5,%6,%7}, {%8,%9}, {%0,%1,%2,%3};"
        : "+f"(c[0]), "+f"(c[1]), "+f"(c[2]), "+f"(c[3])
        : "r"(a[0]), "r"(a[1]), "r"(a[2]), "r"(a[3]), "r"(b[0]), "r"(b[1]));
}
__device__ __forceinline__ uint32_t pack_h2(__half a, __half b) {
    __half2 t = __halves2half2(a, b);
    return *reinterpret_cast<uint32_t*>(&t);
}
// exp2 polynomial (degree-6, rel err <= ~3e-5), FMA-pipe only
__device__ __forceinline__ float exp2p(float t) {
    t = fmaxf(t, -126.f);
    float fl = floorf(t);
    float f = t - fl;
    float p = 1.5403530e-4f;
    p = fmaf(p, f, 1.3333558e-3f);
    p = fmaf(p, f, 9.6181291e-3f);
    p = fmaf(p, f, 5.5504109e-2f);
    p = fmaf(p, f, 2.4022651e-1f);
    p = fmaf(p, f, 6.9314718e-1f);
    p = fmaf(p, f, 1.0f);
    return p * __int_as_float(((int)fl + 127) << 23);
}

// ---------------------------------------------------------------------------
// fp32 -> split fp16 (hi + lo)   and   fp32 -> fp16 (round only)
// ---------------------------------------------------------------------------
__global__ void split_f16_kernel(const float* __restrict__ in,
                                 __half* __restrict__ hi,
                                 __half* __restrict__ lo, int n4)
{
    int i = blockIdx.x * blockDim.x + threadIdx.x;
    if (i >= n4) return;
    float4 v = ((const float4*)in)[i];
    __half hx = __float2half_rn(v.x);
    __half hy = __float2half_rn(v.y);
    __half hz = __float2half_rn(v.z);
    __half hw = __float2half_rn(v.w);
    __half lx = __float2half_rn(v.x - __half2float(hx));
    __half ly = __float2half_rn(v.y - __half2float(hy));
    __half lz = __float2half_rn(v.z - __half2float(hz));
    __half lw = __float2half_rn(v.w - __half2float(hw));
    ((__half2*)hi)[2 * i]     = __halves2half2(hx, hy);
    ((__half2*)hi)[2 * i + 1] = __halves2half2(hz, hw);
    ((__half2*)lo)[2 * i]     = __halves2half2(lx, ly);
    ((__half2*)lo)[2 * i + 1] = __halves2half2(lz, lw);
}
__global__ void conv_f16_kernel(const float* __restrict__ in,
                                __half* __restrict__ hi, int n4)
{
    int i = blockIdx.x * blockDim.x + threadIdx.x;
    if (i >= n4) return;
    float4 v = ((const float4*)in)[i];
    ((__half2*)hi)[2 * i]     = __halves2half2(__float2half_rn(v.x), __float2half_rn(v.y));
    ((__half2*)hi)[2 * i + 1] = __halves2half2(__float2half_rn(v.z), __float2half_rn(v.w));
}

// ---------------------------------------------------------------------------
// Split-fp16 2-pass GEMM: C = (Ah+Al) @ Bh^T + bias  (B-side lo dropped)
// CTA 128(M) x 256(N), 8 warps of 64x64, K-chunk 32, 4-stage ring.
// ---------------------------------------------------------------------------
#define GM_A_BYTES 8192                    // 128 rows x 64 B
#define GM_B_BYTES 16384                   // 256 rows x 64 B
#define GM_STAGE (2 * GM_A_BYTES + GM_B_BYTES)  // 32 KB
#define GM_NSTAGE 4
#define GM_SMEM (GM_NSTAGE * GM_STAGE)     // 128 KB

__device__ __forceinline__ void issue_tile_rows(uint32_t smem_tile,
                                                const __half* __restrict__ G,
                                                int row0, int k0, int K, int tid,
                                                int iters)
{
    for (int t = 0; t < iters; t++) {
        int id = tid + t * 256;
        int r  = id >> 2;
        int c  = id & 3;
        int pc = c ^ ((r >> 1) & 3);
        cp_async16(smem_tile + r * 64 + pc * 16,
                   G + (size_t)(row0 + r) * K + k0 + c * 8);
    }
}
__device__ __forceinline__ void issue_stage(uint32_t base,
                                            const __half* Ah, const __half* Al,
                                            const __half* Bh,
                                            int m0, int n0, int k0, int K, int tid)
{
    issue_tile_rows(base,                  Ah, m0, k0, K, tid, 2);
    issue_tile_rows(base + GM_A_BYTES,     Al, m0, k0, K, tid, 2);
    issue_tile_rows(base + 2 * GM_A_BYTES, Bh, n0, k0, K, tid, 4);
}

__global__ __launch_bounds__(256, 1) void gemm_mma(
    const __half* __restrict__ Ah, const __half* __restrict__ Al,
    const __half* __restrict__ Bh,
    const float* __restrict__ bias, float* __restrict__ Cf,
    __half* __restrict__ Ch, __half* __restrict__ Cl,
    int M, int N, int K)
{
    extern __shared__ char smc[];
    const uint32_t sb = smem_u32(smc);
    const int tid = threadIdx.x;
    const int lane = tid & 31;
    const int wid = tid >> 5;
    const int wm = wid & 1;
    const int wn = wid >> 1;
    const int m0 = blockIdx.y * 128;
    const int n0 = blockIdx.x * 256;

    const int S = K >> 5;

#pragma unroll
    for (int s = 0; s < 3; s++) {
        issue_stage(sb + s * GM_STAGE, Ah, Al, Bh, m0, n0, s * 32, K, tid);
        cp_commit();
    }

    float acc[4][8][4];
#pragma unroll
    for (int i = 0; i < 4; i++)
#pragma unroll
        for (int j = 0; j < 8; j++)
#pragma unroll
            for (int r = 0; r < 4; r++) acc[i][j][r] = 0.f;

    const int a_r = wm * 64 + (lane & 15);
    const int a_c = (lane >> 4);
    const int s_br = (lane & 7) + ((lane >> 4) & 1) * 8;
    const int s_bc = (lane >> 3) & 1;

    for (int s = 0; s < S; s++) {
        cp_wait2();
        __syncthreads();

        if (s + 3 < S)
            issue_stage(sb + ((s + 3) & 3) * GM_STAGE, Ah, Al, Bh,
                        m0, n0, (s + 3) * 32, K, tid);
        cp_commit();

        const uint32_t base = sb + (s & 3) * GM_STAGE;
        const uint32_t tAh = base;
        const uint32_t tAl = base + GM_A_BYTES;
        const uint32_t tBh = base + 2 * GM_A_BYTES;

#pragma unroll
        for (int ks = 0; ks < 2; ks++) {
            uint32_t ah[4][4], al[4][4];
#pragma unroll
            for (int mt = 0; mt < 4; mt++) {
                int r = a_r + mt * 16;
                int pc = (ks * 2 + a_c) ^ ((r >> 1) & 3);
                uint32_t off = r * 64 + pc * 16;
                ldm_x4(ah[mt], tAh + off);
                ldm_x4(al[mt], tAl + off);
            }
#pragma unroll
            for (int g = 0; g < 4; g++) {
                int r = wn * 64 + g * 16 + s_br;
                int pc = (ks * 2 + s_bc) ^ ((r >> 1) & 3);
                uint32_t th[4];
                ldm_x4(th, tBh + r * 64 + pc * 16);
                uint32_t b0[2] = {th[0], th[1]}, b1[2] = {th[2], th[3]};
#pragma unroll
                for (int mt = 0; mt < 4; mt++) {
                    mma_f16(acc[mt][2 * g],     ah[mt], b0);
                    mma_f16(acc[mt][2 * g + 1], ah[mt], b1);
                }
#pragma unroll
                for (int mt = 0; mt < 4; mt++) {
                    mma_f16(acc[mt][2 * g],     al[mt], b0);
                    mma_f16(acc[mt][2 * g + 1], al[mt], b1);
                }
            }
        }
    }

    const int cm = m0 + wm * 64 + (lane >> 2);
    const int cn = n0 + wn * 64 + (lane & 3) * 2;
    if (Cf) {
#pragma unroll
        for (int nt = 0; nt < 8; nt++) {
            float b0 = bias[cn + nt * 8];
            float b1 = bias[cn + nt * 8 + 1];
#pragma unroll
            for (int mt = 0; mt < 4; mt++) {
                float* r0 = Cf + (size_t)(cm + mt * 16) * N + cn + nt * 8;
                float* r1 = r0 + 8 * N;
                *(float2*)r0 = make_float2(acc[mt][nt][0] + b0, acc[mt][nt][1] + b1);
                *(float2*)r1 = make_float2(acc[mt][nt][2] + b0, acc[mt][nt][3] + b1);
            }
        }
    } else {
#pragma unroll
        for (int nt = 0; nt < 8; nt++) {
            float b0 = bias[cn + nt * 8];
            float b1 = bias[cn + nt * 8 + 1];
#pragma unroll
            for (int mt = 0; mt < 4; mt++) {
#pragma unroll
                for (int half = 0; half < 2; half++) {
                    float v0 = acc[mt][nt][2 * half + 0] + b0;
                    float v1 = acc[mt][nt][2 * half + 1] + b1;
                    __half h0 = __float2half_rn(v0);
                    __half h1 = __float2half_rn(v1);
                    __half l0 = __float2half_rn(v0 - __half2float(h0));
                    __half l1 = __float2half_rn(v1 - __half2float(h1));
                    size_t off = (size_t)(cm + mt * 16 + half * 8) * N + cn + nt * 8;
                    *(uint32_t*)(Ch + off) = pack_h2(h0, h1);
                    *(uint32_t*)(Cl + off) = pack_h2(l0, l1);
                }
            }
        }
    }
}

// ---------------------------------------------------------------------------
// fp16 2-pass tensor-core flash attention.
// S = (Qh+Ql)@Kh^T ; ctx = (Ph+Pl)@Vh. 3-buffer ring of 32KB stages.
// ---------------------------------------------------------------------------
#define ATT_STAGE 32768                  // Kh 16K + Vh 16K
#define ATT_SMEM (3 * ATT_STAGE)         // 96 KB (Q transient uses buf0+buf1)
#define ATT_NT 32

__device__ __forceinline__ uint32_t sw_addr(uint32_t base, int r, int c) {
    return base + r * 256 + ((c ^ (r & 7)) << 4);
}
__device__ __forceinline__ void att_load_tile(uint32_t dst,
                                              const __half* __restrict__ g,
                                              int k0, int tid)
{
#pragma unroll
    for (int i = 0; i < 4; i++) {
        int id = tid + i * 256;
        int r = id >> 4;
        int c = id & 15;
        cp_async16(sw_addr(dst, r, c), g + (size_t)(k0 + r) * E3 + c * 8);
    }
}

__global__ __launch_bounds__(256, 1) void attn_tc(
    const __half* __restrict__ qkvh, const __half* __restrict__ qkvl,
    const float* __restrict__ biasM,
    __half* __restrict__ ch, __half* __restrict__ cl)
{
    extern __shared__ char smc[];
    const uint32_t sb = smem_u32(smc);
    const int tid = threadIdx.x;
    const int lane = tid & 31;
    const int wid = tid >> 5;
    const int h = blockIdx.y;
    const int q0 = blockIdx.x * 128;

    const __half* gKh = qkvh + E_DIM + h * D_HEAD;
    const __half* gVh = qkvh + 2 * E_DIM + h * D_HEAD;

    // Q hi -> [sb, +32K), Q lo -> [sb+32K, +32K)  (transient, spans buf0+buf1)
    {
        const __half* gqh = qkvh + (size_t)q0 * E3 + h * D_HEAD;
        const __half* gql = qkvl + (size_t)q0 * E3 + h * D_HEAD;
#pragma unroll
        for (int i = 0; i < 8; i++) {
            int id = tid + i * 256;
            int r = id >> 4;
            int c = id & 15;
            cp_async16(sw_addr(sb, r, c), gqh + (size_t)r * E3 + c * 8);
        }
#pragma unroll
        for (int i = 0; i < 8; i++) {
            int id = tid + i * 256;
            int r = id >> 4;
            int c = id & 15;
            cp_async16(sw_addr(sb + 32768, r, c), gql + (size_t)r * E3 + c * 8);
        }
        cp_commit();
    }
    // k-tile 0 -> buf2
    att_load_tile(sb + 2 * ATT_STAGE,         gKh, 0, tid);
    att_load_tile(sb + 2 * ATT_STAGE + 16384, gVh, 0, tid);
    cp_commit();

    cp_wait1();            // Q ready
    __syncthreads();

    uint32_t qh_f[8][4], ql_f[8][4];
    {
        int r = wid * 16 + (lane & 15);
#pragma unroll
        for (int kf = 0; kf < 8; kf++) {
            int c = 2 * kf + (lane >> 4);
            ldm_x4(qh_f[kf], sw_addr(sb, r, c));
            ldm_x4(ql_f[kf], sw_addr(sb + 32768, r, c));
        }
    }
    __syncthreads();       // all warps done with Q region

    // k-tile 1 -> buf0
    att_load_tile(sb + 0,     gKh, 64, tid);
    att_load_tile(sb + 16384, gVh, 64, tid);
    cp_commit();

    float mA = -INFINITY, mB = -INFINITY, lA = 0.f, lB = 0.f;
    float ctx[16][4];
#pragma unroll
    for (int i = 0; i < 16; i++)
#pragma unroll
        for (int j = 0; j < 4; j++) ctx[i][j] = 0.f;

    const float SCALE = 0.088388347648318447f;
    const float LOG2E = 1.4426950408889634f;
    const int rA = q0 + wid * 16 + (lane >> 2);
    const int rB = rA + 8;
    const int cb = 2 * (lane & 3);

    const int s_br = (lane & 7) + ((lane >> 4) & 1) * 8;
    const int s_bc = (lane >> 3) & 1;
    const int a_r = (lane & 15);
    const int a_c = (lane >> 4);

    for (int kt = 0; kt < ATT_NT; kt++) {
        if (kt < ATT_NT - 2) cp_wait1(); else cp_wait0();
        __syncthreads();
        // tile kt lives in buffer (kt+2)%3
        const uint32_t buf = sb + (uint32_t)(((kt + 2) % 3)) * ATT_STAGE;
        const int k0 = kt * 64;

        // ---- S = scale*(Qh+Ql)@Kh^T + bias (2-pass)
        float sacc[8][4];
#pragma unroll
        for (int i = 0; i < 8; i++)
#pragma unroll
            for (int j = 0; j < 4; j++) sacc[i][j] = 0.f;

#pragma unroll
        for (int kf = 0; kf < 8; kf++) {
#pragma unroll
            for (int ng = 0; ng < 4; ng++) {
                int r = ng * 16 + s_br;
                int c = 2 * kf + s_bc;
                uint32_t th[4];
                ldm_x4(th, sw_addr(buf, r, c));
                uint32_t b0[2] = {th[0], th[1]}, b1[2] = {th[2], th[3]};
                mma_f16(sacc[2 * ng],     qh_f[kf], b0);
                mma_f16(sacc[2 * ng + 1], qh_f[kf], b1);
                mma_f16(sacc[2 * ng],     ql_f[kf], b0);
                mma_f16(sacc[2 * ng + 1], ql_f[kf], b1);
            }
        }

        float mxA = -INFINITY, mxB = -INFINITY;
#pragma unroll
        for (int nt = 0; nt < 8; nt++) {
            float2 bA = *(const float2*)(biasM + (size_t)rA * L_SEQ + k0 + nt * 8 + cb);
            float2 bB = *(const float2*)(biasM + (size_t)rB * L_SEQ + k0 + nt * 8 + cb);
            sacc[nt][0] = fmaf(sacc[nt][0], SCALE, bA.x);
            sacc[nt][1] = fmaf(sacc[nt][1], SCALE, bA.y);
            sacc[nt][2] = fmaf(sacc[nt][2], SCALE, bB.x);
            sacc[nt][3] = fmaf(sacc[nt][3], SCALE, bB.y);
            mxA = fmaxf(mxA, fmaxf(sacc[nt][0], sacc[nt][1]));
            mxB = fmaxf(mxB, fmaxf(sacc[nt][2], sacc[nt][3]));
        }
        mxA = fmaxf(mxA, __shfl_xor_sync(0xffffffffu, mxA, 1));
        mxA = fmaxf(mxA, __shfl_xor_sync(0xffffffffu, mxA, 2));
        mxB = fmaxf(mxB, __shfl_xor_sync(0xffffffffu, mxB, 1));
        mxB = fmaxf(mxB, __shfl_xor_sync(0xffffffffu, mxB, 2));
        float mnA = fmaxf(mA, mxA), mnB = fmaxf(mB, mxB);
        float alA = exp2p((mA - mnA) * LOG2E);
        float alB = exp2p((mB - mnB) * LOG2E);
        float negA = mnA * LOG2E, negB = mnB * LOG2E;
        float sumA = 0.f, sumB = 0.f;
#pragma unroll
        for (int nt = 0; nt < 8; nt++) {
            sacc[nt][0] = exp2p(fmaf(sacc[nt][0], LOG2E, -negA));
            sacc[nt][1] = exp2p(fmaf(sacc[nt][1], LOG2E, -negA));
            sacc[nt][2] = exp2p(fmaf(sacc[nt][2], LOG2E, -negB));
            sacc[nt][3] = exp2p(fmaf(sacc[nt][3], LOG2E, -negB));
            sumA += sacc[nt][0] + sacc[nt][1];
            sumB += sacc[nt][2] + sacc[nt][3];
        }
        sumA += __shfl_xor_sync(0xffffffffu, sumA, 1);
        sumA += __shfl_xor_sync(0xffffffffu, sumA, 2);
        sumB += __shfl_xor_sync(0xffffffffu, sumB, 1);
        sumB += __shfl_xor_sync(0xffffffffu, sumB, 2);
        lA = lA * alA + sumA;
        lB = lB * alB + sumB;
        mA = mnA; mB = mnB;
#pragma unroll
        for (int nt = 0; nt < 16; nt++) {
            ctx[nt][0] *= alA; ctx[nt][1] *= alA;
            ctx[nt][2] *= alB; ctx[nt][3] *= alB;
        }

        // ---- P fragments (fp16 hi/lo, A-operand layout)
        uint32_t pah[4][4], pal[4][4];
#pragma unroll
        for (int kb = 0; kb < 4; kb++) {
#pragma unroll
            for (int half = 0; half < 2; half++) {
#pragma unroll
                for (int sub = 0; sub < 2; sub++) {
                    float p0 = sacc[2 * kb + sub][2 * half + 0];
                    float p1 = sacc[2 * kb + sub][2 * half + 1];
                    __half h0 = __float2half_rn(p0);
                    __half h1 = __float2half_rn(p1);
                    __half l0 = __float2half_rn(p0 - __half2float(h0));
                    __half l1 = __float2half_rn(p1 - __half2float(h1));
                    pah[kb][sub * 2 + half] = pack_h2(h0, h1);
                    pal[kb][sub * 2 + half] = pack_h2(l0, l1);
                }
            }
        }

        // ---- ctx += (Ph+Pl) @ Vh (2-pass), V via ldmatrix.trans
#pragma unroll
        for (int kb = 0; kb < 4; kb++) {
#pragma unroll
            for (int db = 0; db < 8; db++) {
                int r = kb * 16 + a_r;
                int c = 2 * db + a_c;
                uint32_t th[4];
                ldm_x4_t(th, sw_addr(buf + 16384, r, c));
                uint32_t b0[2] = {th[0], th[1]}, b1[2] = {th[2], th[3]};
                mma_f16(ctx[2 * db],     pah[kb], b0);
                mma_f16(ctx[2 * db + 1], pah[kb], b1);
                mma_f16(ctx[2 * db],     pal[kb], b0);
                mma_f16(ctx[2 * db + 1], pal[kb], b1);
            }
        }

        __syncthreads();
        if (kt + 2 < ATT_NT) {
            const uint32_t nbuf = sb + (uint32_t)(((kt + 4) % 3)) * ATT_STAGE;
            const int nk0 = (kt + 2) * 64;
            att_load_tile(nbuf + 0,     gKh, nk0, tid);
            att_load_tile(nbuf + 16384, gVh, nk0, tid);
            cp_commit();
        }
    }

    // ---- epilogue: normalize, split to fp16 h/l, write ctx
    float iA = 1.f / lA, iB = 1.f / lB;
#pragma unroll
    for (int nt = 0; nt < 16; nt++) {
        int col = h * D_HEAD + nt * 8 + cb;
        float v0 = ctx[nt][0] * iA, v1 = ctx[nt][1] * iA;
        float v2 = ctx[nt][2] * iB, v3 = ctx[nt][3] * iB;
        __half h0 = __float2half_rn(v0), h1 = __float2half_rn(v1);
        __half h2 = __float2half_rn(v2), h3 = __float2half_rn(v3);
        __half l0 = __float2half_rn(v0 - __half2float(h0));
        __half l1 = __float2half_rn(v1 - __half2float(h1));
        __half l2 = __float2half_rn(v2 - __half2float(h2));
        __half l3 = __float2half_rn(v3 - __half2float(h3));
        *(uint32_t*)(ch + (size_t)rA * E_DIM + col) = pack_h2(h0, h1);
        *(uint32_t*)(cl + (size_t)rA * E_DIM + col) = pack_h2(l0, l1);
        *(uint32_t*)(ch + (size_t)rB * E_DIM + col) = pack_h2(h2, h3);
        *(uint32_t*)(cl + (size_t)rB * E_DIM + col) = pack_h2(l2, l3);
    }
}

// ---------------------------------------------------------------------------
extern "C" void kernel_launch(void* const* d_in, const int* in_sizes, int n_in,
                              void* d_out, int out_size)
{
    const float* x     = (const float*)d_in[0];
    const float* biasM = (const float*)d_in[1];
    const float* w_in  = (const float*)d_in[2];
    const float* b_in  = (const float*)d_in[3];
    const float* w_out = (const float*)d_in[4];
    const float* b_out = (const float*)d_in[5];
    float* out = (float*)d_out;

    __half *xh, *xl, *wih, *woh, *qkvh, *qkvl, *ch, *cl;
    cudaGetSymbolAddress((void**)&xh, g_xh);
    cudaGetSymbolAddress((void**)&xl, g_xl);
    cudaGetSymbolAddress((void**)&wih, g_wih);
    cudaGetSymbolAddress((void**)&woh, g_woh);
    cudaGetSymbolAddress((void**)&qkvh, g_qkvh);
    cudaGetSymbolAddress((void**)&qkvl, g_qkvl);
    cudaGetSymbolAddress((void**)&ch, g_ch);
    cudaGetSymbolAddress((void**)&cl, g_cl);

    cudaFuncSetAttribute(gemm_mma, cudaFuncAttributeMaxDynamicSharedMemorySize, GM_SMEM);
    cudaFuncSetAttribute(attn_tc, cudaFuncAttributeMaxDynamicSharedMemorySize, ATT_SMEM);

    {
        int n4 = (L_SEQ * E_DIM) / 4;
        split_f16_kernel<<<(n4 + 255) / 256, 256>>>(x, xh, xl, n4);
        int w4 = (E3 * E_DIM) / 4;
        conv_f16_kernel<<<(w4 + 255) / 256, 256>>>(w_in, wih, w4);
        int o4 = (E_DIM * E_DIM) / 4;
        conv_f16_kernel<<<(o4 + 255) / 256, 256>>>(w_out, woh, o4);
    }

    // 1) QKV projection -> split fp16 output   [2048, 6144]
    gemm_mma<<<dim3(E3 / 256, L_SEQ / 128), 256, GM_SMEM>>>(
        xh, xl, wih, b_in, nullptr, qkvh, qkvl, L_SEQ, E3, E_DIM);

    // 2) fp16 2-pass tensor-core attention -> split fp16 ctx
    attn_tc<<<dim3(L_SEQ / 128, H_NUM), 256, ATT_SMEM>>>(
        qkvh, qkvl, biasM, ch, cl);

    // 3) out projection -> fp32 output   [2048, 2048]
    gemm_mma<<<dim3(E_DIM / 256, L_SEQ / 128), 256, GM_SMEM>>>(
        ch, cl, woh, b_out, out, nullptr, nullptr, L_SEQ, E_DIM, E_DIM);
}

// round 10
// speedup vs baseline: 1.5360x; 1.1378x over previous
#include <cuda_runtime.h>
#include <cuda_fp16.h>
#include <cstdint>
#include <math.h>

#define L_SEQ 2048
#define E_DIM 2048
#define H_NUM 16
#define D_HEAD 128
#define E3 6144

// ---------------------------------------------------------------------------
// Device-global scratch (allocation-free rule)
// ---------------------------------------------------------------------------
__device__ __align__(16) __half g_xh[L_SEQ * E_DIM];
__device__ __align__(16) __half g_xl[L_SEQ * E_DIM];
__device__ __align__(16) __half g_wih[E3 * E_DIM];
__device__ __align__(16) __half g_woh[E_DIM * E_DIM];
__device__ __align__(16) __half g_qkvh[L_SEQ * E3];
__device__ __align__(16) __half g_ch[L_SEQ * E_DIM];
__device__ __align__(16) __half g_cl[L_SEQ * E_DIM];

__device__ __forceinline__ uint32_t smem_u32(const void* p) {
    uint32_t a;
    asm("{ .reg .u64 t; cvta.to.shared.u64 t, %1; cvt.u32.u64 %0, t; }" : "=r"(a) : "l"(p));
    return a;
}
__device__ __forceinline__ void cp_async16(uint32_t dst, const void* src) {
    asm volatile("cp.async.cg.shared.global [%0], [%1], 16;" :: "r"(dst), "l"(src));
}
__device__ __forceinline__ void cp_commit() {
    asm volatile("cp.async.commit_group;" ::: "memory");
}
__device__ __forceinline__ void cp_wait2() {
    asm volatile("cp.async.wait_group 2;" ::: "memory");
}
__device__ __forceinline__ void cp_wait1() {
    asm volatile("cp.async.wait_group 1;" ::: "memory");
}
__device__ __forceinline__ void cp_wait0() {
    asm volatile("cp.async.wait_group 0;" ::: "memory");
}
__device__ __forceinline__ void ldm_x4(uint32_t* r, uint32_t addr) {
    asm volatile("ldmatrix.sync.aligned.m8n8.x4.shared.b16 {%0,%1,%2,%3}, [%4];"
                 : "=r"(r[0]), "=r"(r[1]), "=r"(r[2]), "=r"(r[3]) : "r"(addr));
}
__device__ __forceinline__ void ldm_x4_t(uint32_t* r, uint32_t addr) {
    asm volatile("ldmatrix.sync.aligned.m8n8.x4.trans.shared.b16 {%0,%1,%2,%3}, [%4];"
                 : "=r"(r[0]), "=r"(r[1]), "=r"(r[2]), "=r"(r[3]) : "r"(addr));
}
__device__ __forceinline__ void mma_f16(float* c, const uint32_t* a, const uint32_t* b) {
    asm("mma.sync.aligned.m16n8k16.row.col.f32.f16.f16.f32 "
        "{%0,%1,%2,%3}, {%4,%5,%6,%7}, {%8,%9}, {%0,%1,%2,%3};"
        : "+f"(c[0]), "+f"(c[1]), "+f"(c[2]), "+f"(c[3])
        : "r"(a[0]), "r"(a[1]), "r"(a[2]), "r"(a[3]), "r"(b[0]), "r"(b[1]));
}
__device__ __forceinline__ uint32_t pack_h2(__half a, __half b) {
    __half2 t = __halves2half2(a, b);
    return *reinterpret_cast<uint32_t*>(&t);
}
// exp2 polynomial (degree-6, rel err <= ~3e-5), FMA-pipe only
__device__ __forceinline__ float exp2p(float t) {
    t = fmaxf(t, -126.f);
    float fl = floorf(t);
    float f = t - fl;
    float p = 1.5403530e-4f;
    p = fmaf(p, f, 1.3333558e-3f);
    p = fmaf(p, f, 9.6181291e-3f);
    p = fmaf(p, f, 5.5504109e-2f);
    p = fmaf(p, f, 2.4022651e-1f);
    p = fmaf(p, f, 6.9314718e-1f);
    p = fmaf(p, f, 1.0f);
    return p * __int_as_float(((int)fl + 127) << 23);
}

// ---------------------------------------------------------------------------
// fp32 -> split fp16 (hi + lo)   and   fp32 -> fp16 (round only)
// ---------------------------------------------------------------------------
__global__ void split_f16_kernel(const float* __restrict__ in,
                                 __half* __restrict__ hi,
                                 __half* __restrict__ lo, int n4)
{
    int i = blockIdx.x * blockDim.x + threadIdx.x;
    if (i >= n4) return;
    float4 v = ((const float4*)in)[i];
    __half hx = __float2half_rn(v.x);
    __half hy = __float2half_rn(v.y);
    __half hz = __float2half_rn(v.z);
    __half hw = __float2half_rn(v.w);
    __half lx = __float2half_rn(v.x - __half2float(hx));
    __half ly = __float2half_rn(v.y - __half2float(hy));
    __half lz = __float2half_rn(v.z - __half2float(hz));
    __half lw = __float2half_rn(v.w - __half2float(hw));
    ((__half2*)hi)[2 * i]     = __halves2half2(hx, hy);
    ((__half2*)hi)[2 * i + 1] = __halves2half2(hz, hw);
    ((__half2*)lo)[2 * i]     = __halves2half2(lx, ly);
    ((__half2*)lo)[2 * i + 1] = __halves2half2(lz, lw);
}
__global__ void conv_f16_kernel(const float* __restrict__ in,
                                __half* __restrict__ hi, int n4)
{
    int i = blockIdx.x * blockDim.x + threadIdx.x;
    if (i >= n4) return;
    float4 v = ((const float4*)in)[i];
    ((__half2*)hi)[2 * i]     = __halves2half2(__float2half_rn(v.x), __float2half_rn(v.y));
    ((__half2*)hi)[2 * i + 1] = __halves2half2(__float2half_rn(v.z), __float2half_rn(v.w));
}

// ---------------------------------------------------------------------------
// Split-fp16 2-pass GEMM: C = (Ah+Al) @ Bh^T + bias.
// CTA 128x128, 8 warps of 64x32, 4-stage ring (24KB/stage), 2 CTAs/SM.
// ---------------------------------------------------------------------------
#define GM_TILE_BYTES 8192
#define GM_STAGE (3 * GM_TILE_BYTES)       // Ah, Al, Bh = 24 KB
#define GM_NSTAGE 4
#define GM_SMEM (GM_NSTAGE * GM_STAGE)     // 96 KB per CTA

__device__ __forceinline__ void issue_tile(uint32_t smem_tile,
                                           const __half* __restrict__ G,
                                           int row0, int k0, int K, int tid)
{
#pragma unroll
    for (int t = 0; t < 2; t++) {
        int id = tid + t * 256;
        int r  = id >> 2;
        int c  = id & 3;
        int pc = c ^ ((r >> 1) & 3);
        cp_async16(smem_tile + r * 64 + pc * 16,
                   G + (size_t)(row0 + r) * K + k0 + c * 8);
    }
}
__device__ __forceinline__ void issue_stage(uint32_t base,
                                            const __half* Ah, const __half* Al,
                                            const __half* Bh,
                                            int m0, int n0, int k0, int K, int tid)
{
    issue_tile(base,                     Ah, m0, k0, K, tid);
    issue_tile(base + GM_TILE_BYTES,     Al, m0, k0, K, tid);
    issue_tile(base + 2 * GM_TILE_BYTES, Bh, n0, k0, K, tid);
}

__global__ __launch_bounds__(256, 2) void gemm_mma(
    const __half* __restrict__ Ah, const __half* __restrict__ Al,
    const __half* __restrict__ Bh,
    const float* __restrict__ bias, float* __restrict__ Cf,
    __half* __restrict__ Ch, __half* __restrict__ Cl,
    int M, int N, int K)
{
    extern __shared__ char smc[];
    const uint32_t sb = smem_u32(smc);
    const int tid = threadIdx.x;
    const int lane = tid & 31;
    const int wid = tid >> 5;
    const int wm = wid & 1;
    const int wn = wid >> 1;
    const int m0 = blockIdx.y * 128;
    const int n0 = blockIdx.x * 128;

    const int S = K >> 5;

#pragma unroll
    for (int s = 0; s < 3; s++) {
        issue_stage(sb + s * GM_STAGE, Ah, Al, Bh, m0, n0, s * 32, K, tid);
        cp_commit();
    }

    float acc[4][4][4];
#pragma unroll
    for (int i = 0; i < 4; i++)
#pragma unroll
        for (int j = 0; j < 4; j++)
#pragma unroll
            for (int r = 0; r < 4; r++) acc[i][j][r] = 0.f;

    const int a_r = wm * 64 + (lane & 15);
    const int a_c = (lane >> 4);
    const int b_sub = lane >> 3;
    const int b_r = wn * 32 + (lane & 7) + (b_sub >> 1) * 8;
    const int b_c = (b_sub & 1);

    for (int s = 0; s < S; s++) {
        cp_wait2();
        __syncthreads();

        if (s + 3 < S)
            issue_stage(sb + ((s + 3) & 3) * GM_STAGE, Ah, Al, Bh,
                        m0, n0, (s + 3) * 32, K, tid);
        cp_commit();

        const uint32_t base = sb + (s & 3) * GM_STAGE;
        const uint32_t tAh = base;
        const uint32_t tAl = base + GM_TILE_BYTES;
        const uint32_t tBh = base + 2 * GM_TILE_BYTES;

#pragma unroll
        for (int ks = 0; ks < 2; ks++) {
            uint32_t ah[4][4], al[4][4], bh[4][2];
#pragma unroll
            for (int mt = 0; mt < 4; mt++) {
                int r = a_r + mt * 16;
                int pc = (ks * 2 + a_c) ^ ((r >> 1) & 3);
                uint32_t off = r * 64 + pc * 16;
                ldm_x4(ah[mt], tAh + off);
                ldm_x4(al[mt], tAl + off);
            }
#pragma unroll
            for (int g = 0; g < 2; g++) {
                int r = b_r + g * 16;
                int pc = (ks * 2 + b_c) ^ ((r >> 1) & 3);
                uint32_t th[4];
                ldm_x4(th, tBh + r * 64 + pc * 16);
                bh[g * 2][0] = th[0]; bh[g * 2][1] = th[1];
                bh[g * 2 + 1][0] = th[2]; bh[g * 2 + 1][1] = th[3];
            }
#pragma unroll
            for (int mt = 0; mt < 4; mt++)
#pragma unroll
                for (int nt = 0; nt < 4; nt++)
                    mma_f16(acc[mt][nt], ah[mt], bh[nt]);
#pragma unroll
            for (int mt = 0; mt < 4; mt++)
#pragma unroll
                for (int nt = 0; nt < 4; nt++)
                    mma_f16(acc[mt][nt], al[mt], bh[nt]);
        }
    }

    const int cm = m0 + wm * 64 + (lane >> 2);
    const int cn = n0 + wn * 32 + (lane & 3) * 2;
    if (Cf) {
#pragma unroll
        for (int nt = 0; nt < 4; nt++) {
            float b0 = bias[cn + nt * 8];
            float b1 = bias[cn + nt * 8 + 1];
#pragma unroll
            for (int mt = 0; mt < 4; mt++) {
                float* r0 = Cf + (size_t)(cm + mt * 16) * N + cn + nt * 8;
                float* r1 = r0 + 8 * N;
                *(float2*)r0 = make_float2(acc[mt][nt][0] + b0, acc[mt][nt][1] + b1);
                *(float2*)r1 = make_float2(acc[mt][nt][2] + b0, acc[mt][nt][3] + b1);
            }
        }
    } else {
#pragma unroll
        for (int nt = 0; nt < 4; nt++) {
            float b0 = bias[cn + nt * 8];
            float b1 = bias[cn + nt * 8 + 1];
#pragma unroll
            for (int mt = 0; mt < 4; mt++) {
#pragma unroll
                for (int half = 0; half < 2; half++) {
                    float v0 = acc[mt][nt][2 * half + 0] + b0;
                    float v1 = acc[mt][nt][2 * half + 1] + b1;
                    __half h0 = __float2half_rn(v0);
                    __half h1 = __float2half_rn(v1);
                    size_t off = (size_t)(cm + mt * 16 + half * 8) * N + cn + nt * 8;
                    *(uint32_t*)(Ch + off) = pack_h2(h0, h1);
                    if (Cl) {
                        __half l0 = __float2half_rn(v0 - __half2float(h0));
                        __half l1 = __float2half_rn(v1 - __half2float(h1));
                        *(uint32_t*)(Cl + off) = pack_h2(l0, l1);
                    }
                }
            }
        }
    }
}

// ---------------------------------------------------------------------------
// fp16 1-pass tensor-core flash attention: S = Qh@Kh^T ; ctx = Ph@Vh.
// 3-buffer ring of 32KB K/V stages; Q (hi only) transient in buf0.
// ---------------------------------------------------------------------------
#define ATT_STAGE 32768                  // Kh 16K + Vh 16K
#define ATT_SMEM (3 * ATT_STAGE)         // 96 KB
#define ATT_NT 32

__device__ __forceinline__ uint32_t sw_addr(uint32_t base, int r, int c) {
    return base + r * 256 + ((c ^ (r & 7)) << 4);
}
__device__ __forceinline__ void att_load_tile(uint32_t dst,
                                              const __half* __restrict__ g,
                                              int k0, int tid)
{
#pragma unroll
    for (int i = 0; i < 4; i++) {
        int id = tid + i * 256;
        int r = id >> 4;
        int c = id & 15;
        cp_async16(sw_addr(dst, r, c), g + (size_t)(k0 + r) * E3 + c * 8);
    }
}

__global__ __launch_bounds__(256, 1) void attn_tc(
    const __half* __restrict__ qkvh,
    const float* __restrict__ biasM,
    __half* __restrict__ ch, __half* __restrict__ cl)
{
    extern __shared__ char smc[];
    const uint32_t sb = smem_u32(smc);
    const int tid = threadIdx.x;
    const int lane = tid & 31;
    const int wid = tid >> 5;
    const int h = blockIdx.y;
    const int q0 = blockIdx.x * 128;

    const __half* gKh = qkvh + E_DIM + h * D_HEAD;
    const __half* gVh = qkvh + 2 * E_DIM + h * D_HEAD;

    // Q hi -> buf0 (32 KB, transient)
    {
        const __half* gqh = qkvh + (size_t)q0 * E3 + h * D_HEAD;
#pragma unroll
        for (int i = 0; i < 8; i++) {
            int id = tid + i * 256;
            int r = id >> 4;
            int c = id & 15;
            cp_async16(sw_addr(sb, r, c), gqh + (size_t)r * E3 + c * 8);
        }
        cp_commit();
    }
    // k-tile 0 -> buf1
    att_load_tile(sb + ATT_STAGE,         gKh, 0, tid);
    att_load_tile(sb + ATT_STAGE + 16384, gVh, 0, tid);
    cp_commit();

    cp_wait1();            // Q ready (k0 may be in flight)
    __syncthreads();

    uint32_t qh_f[8][4];
    {
        int r = wid * 16 + (lane & 15);
#pragma unroll
        for (int kf = 0; kf < 8; kf++) {
            int c = 2 * kf + (lane >> 4);
            ldm_x4(qh_f[kf], sw_addr(sb, r, c));
        }
    }
    __syncthreads();       // all warps done with Q region (buf0 reusable)

    // k-tile 1 -> buf2
    att_load_tile(sb + 2 * ATT_STAGE,         gKh, 64, tid);
    att_load_tile(sb + 2 * ATT_STAGE + 16384, gVh, 64, tid);
    cp_commit();

    float mA = -INFINITY, mB = -INFINITY, lA = 0.f, lB = 0.f;
    float ctx[16][4];
#pragma unroll
    for (int i = 0; i < 16; i++)
#pragma unroll
        for (int j = 0; j < 4; j++) ctx[i][j] = 0.f;

    const float SCALE = 0.088388347648318447f;
    const float LOG2E = 1.4426950408889634f;
    const int rA = q0 + wid * 16 + (lane >> 2);
    const int rB = rA + 8;
    const int cb = 2 * (lane & 3);

    const int s_br = (lane & 7) + ((lane >> 4) & 1) * 8;
    const int s_bc = (lane >> 3) & 1;
    const int a_r = (lane & 15);
    const int a_c = (lane >> 4);

    for (int kt = 0; kt < ATT_NT; kt++) {
        if (kt < ATT_NT - 2) cp_wait1(); else cp_wait0();
        __syncthreads();
        // tile kt lives in buffer (kt+1)%3
        const uint32_t buf = sb + (uint32_t)(((kt + 1) % 3)) * ATT_STAGE;
        const int k0 = kt * 64;

        // ---- S = scale * Qh @ Kh^T + bias (1-pass)
        float sacc[8][4];
#pragma unroll
        for (int i = 0; i < 8; i++)
#pragma unroll
            for (int j = 0; j < 4; j++) sacc[i][j] = 0.f;

#pragma unroll
        for (int kf = 0; kf < 8; kf++) {
#pragma unroll
            for (int ng = 0; ng < 4; ng++) {
                int r = ng * 16 + s_br;
                int c = 2 * kf + s_bc;
                uint32_t th[4];
                ldm_x4(th, sw_addr(buf, r, c));
                uint32_t b0[2] = {th[0], th[1]}, b1[2] = {th[2], th[3]};
                mma_f16(sacc[2 * ng],     qh_f[kf], b0);
                mma_f16(sacc[2 * ng + 1], qh_f[kf], b1);
            }
        }

        float mxA = -INFINITY, mxB = -INFINITY;
#pragma unroll
        for (int nt = 0; nt < 8; nt++) {
            float2 bA = *(const float2*)(biasM + (size_t)rA * L_SEQ + k0 + nt * 8 + cb);
            float2 bB = *(const float2*)(biasM + (size_t)rB * L_SEQ + k0 + nt * 8 + cb);
            sacc[nt][0] = fmaf(sacc[nt][0], SCALE, bA.x);
            sacc[nt][1] = fmaf(sacc[nt][1], SCALE, bA.y);
            sacc[nt][2] = fmaf(sacc[nt][2], SCALE, bB.x);
            sacc[nt][3] = fmaf(sacc[nt][3], SCALE, bB.y);
            mxA = fmaxf(mxA, fmaxf(sacc[nt][0], sacc[nt][1]));
            mxB = fmaxf(mxB, fmaxf(sacc[nt][2], sacc[nt][3]));
        }
        mxA = fmaxf(mxA, __shfl_xor_sync(0xffffffffu, mxA, 1));
        mxA = fmaxf(mxA, __shfl_xor_sync(0xffffffffu, mxA, 2));
        mxB = fmaxf(mxB, __shfl_xor_sync(0xffffffffu, mxB, 1));
        mxB = fmaxf(mxB, __shfl_xor_sync(0xffffffffu, mxB, 2));
        float mnA = fmaxf(mA, mxA), mnB = fmaxf(mB, mxB);
        float alA = exp2p((mA - mnA) * LOG2E);
        float alB = exp2p((mB - mnB) * LOG2E);
        float negA = mnA * LOG2E, negB = mnB * LOG2E;
        float sumA = 0.f, sumB = 0.f;
#pragma unroll
        for (int nt = 0; nt < 8; nt++) {
            sacc[nt][0] = exp2p(fmaf(sacc[nt][0], LOG2E, -negA));
            sacc[nt][1] = exp2p(fmaf(sacc[nt][1], LOG2E, -negA));
            sacc[nt][2] = exp2p(fmaf(sacc[nt][2], LOG2E, -negB));
            sacc[nt][3] = exp2p(fmaf(sacc[nt][3], LOG2E, -negB));
            sumA += sacc[nt][0] + sacc[nt][1];
            sumB += sacc[nt][2] + sacc[nt][3];
        }
        sumA += __shfl_xor_sync(0xffffffffu, sumA, 1);
        sumA += __shfl_xor_sync(0xffffffffu, sumA, 2);
        sumB += __shfl_xor_sync(0xffffffffu, sumB, 1);
        sumB += __shfl_xor_sync(0xffffffffu, sumB, 2);
        lA = lA * alA + sumA;
        lB = lB * alB + sumB;
        mA = mnA; mB = mnB;
#pragma unroll
        for (int nt = 0; nt < 16; nt++) {
            ctx[nt][0] *= alA; ctx[nt][1] *= alA;
            ctx[nt][2] *= alB; ctx[nt][3] *= alB;
        }

        // ---- P fragments (single fp16 rounding)
        uint32_t pah[4][4];
#pragma unroll
        for (int kb = 0; kb < 4; kb++) {
#pragma unroll
            for (int half = 0; half < 2; half++) {
#pragma unroll
                for (int sub = 0; sub < 2; sub++) {
                    float p0 = sacc[2 * kb + sub][2 * half + 0];
                    float p1 = sacc[2 * kb + sub][2 * half + 1];
                    pah[kb][sub * 2 + half] =
                        pack_h2(__float2half_rn(p0), __float2half_rn(p1));
                }
            }
        }

        // ---- ctx += Ph @ Vh (1-pass), V via ldmatrix.trans
#pragma unroll
        for (int kb = 0; kb < 4; kb++) {
#pragma unroll
            for (int db = 0; db < 8; db++) {
                int r = kb * 16 + a_r;
                int c = 2 * db + a_c;
                uint32_t th[4];
                ldm_x4_t(th, sw_addr(buf + 16384, r, c));
                uint32_t b0[2] = {th[0], th[1]}, b1[2] = {th[2], th[3]};
                mma_f16(ctx[2 * db],     pah[kb], b0);
                mma_f16(ctx[2 * db + 1], pah[kb], b1);
            }
        }

        __syncthreads();
        if (kt + 2 < ATT_NT) {
            const uint32_t nbuf = sb + (uint32_t)((kt % 3)) * ATT_STAGE;
            const int nk0 = (kt + 2) * 64;
            att_load_tile(nbuf + 0,     gKh, nk0, tid);
            att_load_tile(nbuf + 16384, gVh, nk0, tid);
            cp_commit();
        } else {
            cp_commit();
        }
    }

    // ---- epilogue: normalize, split to fp16 h/l (for gemm2), write ctx
    float iA = 1.f / lA, iB = 1.f / lB;
#pragma unroll
    for (int nt = 0; nt < 16; nt++) {
        int col = h * D_HEAD + nt * 8 + cb;
        float v0 = ctx[nt][0] * iA, v1 = ctx[nt][1] * iA;
        float v2 = ctx[nt][2] * iB, v3 = ctx[nt][3] * iB;
        __half h0 = __float2half_rn(v0), h1 = __float2half_rn(v1);
        __half h2 = __float2half_rn(v2), h3 = __float2half_rn(v3);
        __half l0 = __float2half_rn(v0 - __half2float(h0));
        __half l1 = __float2half_rn(v1 - __half2float(h1));
        __half l2 = __float2half_rn(v2 - __half2float(h2));
        __half l3 = __float2half_rn(v3 - __half2float(h3));
        *(uint32_t*)(ch + (size_t)rA * E_DIM + col) = pack_h2(h0, h1);
        *(uint32_t*)(cl + (size_t)rA * E_DIM + col) = pack_h2(l0, l1);
        *(uint32_t*)(ch + (size_t)rB * E_DIM + col) = pack_h2(h2, h3);
        *(uint32_t*)(cl + (size_t)rB * E_DIM + col) = pack_h2(l2, l3);
    }
}

// ---------------------------------------------------------------------------
extern "C" void kernel_launch(void* const* d_in, const int* in_sizes, int n_in,
                              void* d_out, int out_size)
{
    const float* x     = (const float*)d_in[0];
    const float* biasM = (const float*)d_in[1];
    const float* w_in  = (const float*)d_in[2];
    const float* b_in  = (const float*)d_in[3];
    const float* w_out = (const float*)d_in[4];
    const float* b_out = (const float*)d_in[5];
    float* out = (float*)d_out;

    __half *xh, *xl, *wih, *woh, *qkvh, *ch, *cl;
    cudaGetSymbolAddress((void**)&xh, g_xh);
    cudaGetSymbolAddress((void**)&xl, g_xl);
    cudaGetSymbolAddress((void**)&wih, g_wih);
    cudaGetSymbolAddress((void**)&woh, g_woh);
    cudaGetSymbolAddress((void**)&qkvh, g_qkvh);
    cudaGetSymbolAddress((void**)&ch, g_ch);
    cudaGetSymbolAddress((void**)&cl, g_cl);

    cudaFuncSetAttribute(gemm_mma, cudaFuncAttributeMaxDynamicSharedMemorySize, GM_SMEM);
    cudaFuncSetAttribute(attn_tc, cudaFuncAttributeMaxDynamicSharedMemorySize, ATT_SMEM);

    {
        int n4 = (L_SEQ * E_DIM) / 4;
        split_f16_kernel<<<(n4 + 255) / 256, 256>>>(x, xh, xl, n4);
        int w4 = (E3 * E_DIM) / 4;
        conv_f16_kernel<<<(w4 + 255) / 256, 256>>>(w_in, wih, w4);
        int o4 = (E_DIM * E_DIM) / 4;
        conv_f16_kernel<<<(o4 + 255) / 256, 256>>>(w_out, woh, o4);
    }

    // 1) QKV projection -> fp16 hi only   [2048, 6144]
    gemm_mma<<<dim3(E3 / 128, L_SEQ / 128), 256, GM_SMEM>>>(
        xh, xl, wih, b_in, nullptr, qkvh, nullptr, L_SEQ, E3, E_DIM);

    // 2) fp16 1-pass tensor-core attention -> split fp16 ctx
    attn_tc<<<dim3(L_SEQ / 128, H_NUM), 256, ATT_SMEM>>>(
        qkvh, biasM, ch, cl);

    // 3) out projection -> fp32 output   [2048, 2048]
    gemm_mma<<<dim3(E_DIM / 128, L_SEQ / 128), 256, GM_SMEM>>>(
        ch, cl, woh, b_out, out, nullptr, nullptr, L_SEQ, E_DIM, E_DIM);
}

// round 11
// speedup vs baseline: 2.0949x; 1.3638x over previous
#include <cuda_runtime.h>
#include <cuda_fp16.h>
#include <cstdint>
#include <math.h>

#define L_SEQ 2048
#define E_DIM 2048
#define H_NUM 16
#define D_HEAD 128
#define E3 6144

// ---------------------------------------------------------------------------
// Device-global scratch (allocation-free rule)
// ---------------------------------------------------------------------------
__device__ __align__(16) __half g_xh[L_SEQ * E_DIM];
__device__ __align__(16) __half g_wih[E3 * E_DIM];
__device__ __align__(16) __half g_woh[E_DIM * E_DIM];
__device__ __align__(16) __half g_qkvh[L_SEQ * E3];
__device__ __align__(16) __half g_ch[L_SEQ * E_DIM];

__device__ __forceinline__ uint32_t smem_u32(const void* p) {
    uint32_t a;
    asm("{ .reg .u64 t; cvta.to.shared.u64 t, %1; cvt.u32.u64 %0, t; }" : "=r"(a) : "l"(p));
    return a;
}
__device__ __forceinline__ void cp_async16(uint32_t dst, const void* src) {
    asm volatile("cp.async.cg.shared.global [%0], [%1], 16;" :: "r"(dst), "l"(src));
}
__device__ __forceinline__ void cp_commit() {
    asm volatile("cp.async.commit_group;" ::: "memory");
}
__device__ __forceinline__ void cp_wait2() {
    asm volatile("cp.async.wait_group 2;" ::: "memory");
}
__device__ __forceinline__ void cp_wait1() {
    asm volatile("cp.async.wait_group 1;" ::: "memory");
}
__device__ __forceinline__ void cp_wait0() {
    asm volatile("cp.async.wait_group 0;" ::: "memory");
}
__device__ __forceinline__ void ldm_x4(uint32_t* r, uint32_t addr) {
    asm volatile("ldmatrix.sync.aligned.m8n8.x4.shared.b16 {%0,%1,%2,%3}, [%4];"
                 : "=r"(r[0]), "=r"(r[1]), "=r"(r[2]), "=r"(r[3]) : "r"(addr));
}
__device__ __forceinline__ void ldm_x4_t(uint32_t* r, uint32_t addr) {
    asm volatile("ldmatrix.sync.aligned.m8n8.x4.trans.shared.b16 {%0,%1,%2,%3}, [%4];"
                 : "=r"(r[0]), "=r"(r[1]), "=r"(r[2]), "=r"(r[3]) : "r"(addr));
}
__device__ __forceinline__ void mma_f16(float* c, const uint32_t* a, const uint32_t* b) {
    asm("mma.sync.aligned.m16n8k16.row.col.f32.f16.f16.f32 "
        "{%0,%1,%2,%3}, {%4,%5,%6,%7}, {%8,%9}, {%0,%1,%2,%3};"
        : "+f"(c[0]), "+f"(c[1]), "+f"(c[2]), "+f"(c[3])
        : "r"(a[0]), "r"(a[1]), "r"(a[2]), "r"(a[3]), "r"(b[0]), "r"(b[1]));
}
__device__ __forceinline__ uint32_t pack_h2(__half a, __half b) {
    __half2 t = __halves2half2(a, b);
    return *reinterpret_cast<uint32_t*>(&t);
}
// exp2 polynomial (degree-6, rel err <= ~3e-5), FMA-pipe only
__device__ __forceinline__ float exp2p(float t) {
    t = fmaxf(t, -126.f);
    float fl = floorf(t);
    float f = t - fl;
    float p = 1.5403530e-4f;
    p = fmaf(p, f, 1.3333558e-3f);
    p = fmaf(p, f, 9.6181291e-3f);
    p = fmaf(p, f, 5.5504109e-2f);
    p = fmaf(p, f, 2.4022651e-1f);
    p = fmaf(p, f, 6.9314718e-1f);
    p = fmaf(p, f, 1.0f);
    return p * __int_as_float(((int)fl + 127) << 23);
}

// ---------------------------------------------------------------------------
// fp32 -> fp16 convert
// ---------------------------------------------------------------------------
__global__ void conv_f16_kernel(const float* __restrict__ in,
                                __half* __restrict__ hi, int n4)
{
    int i = blockIdx.x * blockDim.x + threadIdx.x;
    if (i >= n4) return;
    float4 v = ((const float4*)in)[i];
    ((__half2*)hi)[2 * i]     = __halves2half2(__float2half_rn(v.x), __float2half_rn(v.y));
    ((__half2*)hi)[2 * i + 1] = __halves2half2(__float2half_rn(v.z), __float2half_rn(v.w));
}

// ---------------------------------------------------------------------------
// fp16 1-pass GEMM: C = A @ B^T + bias.
// CTA 128x128, 8 warps of 64x32, 4-stage ring (16KB/stage), 2 CTAs/SM.
// ---------------------------------------------------------------------------
#define GM_TILE_BYTES 8192
#define GM_STAGE (2 * GM_TILE_BYTES)       // A, B = 16 KB
#define GM_NSTAGE 4
#define GM_SMEM (GM_NSTAGE * GM_STAGE)     // 64 KB per CTA

__device__ __forceinline__ void issue_tile(uint32_t smem_tile,
                                           const __half* __restrict__ G,
                                           int row0, int k0, int K, int tid)
{
#pragma unroll
    for (int t = 0; t < 2; t++) {
        int id = tid + t * 256;
        int r  = id >> 2;
        int c  = id & 3;
        int pc = c ^ ((r >> 1) & 3);
        cp_async16(smem_tile + r * 64 + pc * 16,
                   G + (size_t)(row0 + r) * K + k0 + c * 8);
    }
}
__device__ __forceinline__ void issue_stage(uint32_t base,
                                            const __half* A, const __half* B,
                                            int m0, int n0, int k0, int K, int tid)
{
    issue_tile(base,                 A, m0, k0, K, tid);
    issue_tile(base + GM_TILE_BYTES, B, n0, k0, K, tid);
}

__global__ __launch_bounds__(256, 2) void gemm_mma(
    const __half* __restrict__ A, const __half* __restrict__ B,
    const float* __restrict__ bias, float* __restrict__ Cf,
    __half* __restrict__ Ch,
    int M, int N, int K)
{
    extern __shared__ char smc[];
    const uint32_t sb = smem_u32(smc);
    const int tid = threadIdx.x;
    const int lane = tid & 31;
    const int wid = tid >> 5;
    const int wm = wid & 1;
    const int wn = wid >> 1;
    const int m0 = blockIdx.y * 128;
    const int n0 = blockIdx.x * 128;

    const int S = K >> 5;

#pragma unroll
    for (int s = 0; s < 3; s++) {
        issue_stage(sb + s * GM_STAGE, A, B, m0, n0, s * 32, K, tid);
        cp_commit();
    }

    float acc[4][4][4];
#pragma unroll
    for (int i = 0; i < 4; i++)
#pragma unroll
        for (int j = 0; j < 4; j++)
#pragma unroll
            for (int r = 0; r < 4; r++) acc[i][j][r] = 0.f;

    const int a_r = wm * 64 + (lane & 15);
    const int a_c = (lane >> 4);
    const int b_sub = lane >> 3;
    const int b_r = wn * 32 + (lane & 7) + (b_sub >> 1) * 8;
    const int b_c = (b_sub & 1);

    for (int s = 0; s < S; s++) {
        cp_wait2();
        __syncthreads();

        if (s + 3 < S)
            issue_stage(sb + ((s + 3) & 3) * GM_STAGE, A, B,
                        m0, n0, (s + 3) * 32, K, tid);
        cp_commit();

        const uint32_t base = sb + (s & 3) * GM_STAGE;
        const uint32_t tA = base;
        const uint32_t tB = base + GM_TILE_BYTES;

#pragma unroll
        for (int ks = 0; ks < 2; ks++) {
            uint32_t ah[4][4], bh[4][2];
#pragma unroll
            for (int mt = 0; mt < 4; mt++) {
                int r = a_r + mt * 16;
                int pc = (ks * 2 + a_c) ^ ((r >> 1) & 3);
                ldm_x4(ah[mt], tA + r * 64 + pc * 16);
            }
#pragma unroll
            for (int g = 0; g < 2; g++) {
                int r = b_r + g * 16;
                int pc = (ks * 2 + b_c) ^ ((r >> 1) & 3);
                uint32_t th[4];
                ldm_x4(th, tB + r * 64 + pc * 16);
                bh[g * 2][0] = th[0]; bh[g * 2][1] = th[1];
                bh[g * 2 + 1][0] = th[2]; bh[g * 2 + 1][1] = th[3];
            }
#pragma unroll
            for (int mt = 0; mt < 4; mt++)
#pragma unroll
                for (int nt = 0; nt < 4; nt++)
                    mma_f16(acc[mt][nt], ah[mt], bh[nt]);
        }
    }

    const int cm = m0 + wm * 64 + (lane >> 2);
    const int cn = n0 + wn * 32 + (lane & 3) * 2;
    if (Cf) {
#pragma unroll
        for (int nt = 0; nt < 4; nt++) {
            float b0 = bias[cn + nt * 8];
            float b1 = bias[cn + nt * 8 + 1];
#pragma unroll
            for (int mt = 0; mt < 4; mt++) {
                float* r0 = Cf + (size_t)(cm + mt * 16) * N + cn + nt * 8;
                float* r1 = r0 + 8 * N;
                *(float2*)r0 = make_float2(acc[mt][nt][0] + b0, acc[mt][nt][1] + b1);
                *(float2*)r1 = make_float2(acc[mt][nt][2] + b0, acc[mt][nt][3] + b1);
            }
        }
    } else {
#pragma unroll
        for (int nt = 0; nt < 4; nt++) {
            float b0 = bias[cn + nt * 8];
            float b1 = bias[cn + nt * 8 + 1];
#pragma unroll
            for (int mt = 0; mt < 4; mt++) {
#pragma unroll
                for (int half = 0; half < 2; half++) {
                    float v0 = acc[mt][nt][2 * half + 0] + b0;
                    float v1 = acc[mt][nt][2 * half + 1] + b1;
                    size_t off = (size_t)(cm + mt * 16 + half * 8) * N + cn + nt * 8;
                    *(uint32_t*)(Ch + off) =
                        pack_h2(__float2half_rn(v0), __float2half_rn(v1));
                }
            }
        }
    }
}

// ---------------------------------------------------------------------------
// fp16 1-pass tensor-core flash attention: S = Qh@Kh^T ; ctx = Ph@Vh.
// 3-buffer ring of 32KB K/V stages; Q (hi only) transient in buf0.
// ---------------------------------------------------------------------------
#define ATT_STAGE 32768                  // Kh 16K + Vh 16K
#define ATT_SMEM (3 * ATT_STAGE)         // 96 KB
#define ATT_NT 32

__device__ __forceinline__ uint32_t sw_addr(uint32_t base, int r, int c) {
    return base + r * 256 + ((c ^ (r & 7)) << 4);
}
__device__ __forceinline__ void att_load_tile(uint32_t dst,
                                              const __half* __restrict__ g,
                                              int k0, int tid)
{
#pragma unroll
    for (int i = 0; i < 4; i++) {
        int id = tid + i * 256;
        int r = id >> 4;
        int c = id & 15;
        cp_async16(sw_addr(dst, r, c), g + (size_t)(k0 + r) * E3 + c * 8);
    }
}

__global__ __launch_bounds__(256, 1) void attn_tc(
    const __half* __restrict__ qkvh,
    const float* __restrict__ biasM,
    __half* __restrict__ ch)
{
    extern __shared__ char smc[];
    const uint32_t sb = smem_u32(smc);
    const int tid = threadIdx.x;
    const int lane = tid & 31;
    const int wid = tid >> 5;
    const int h = blockIdx.y;
    const int q0 = blockIdx.x * 128;

    const __half* gKh = qkvh + E_DIM + h * D_HEAD;
    const __half* gVh = qkvh + 2 * E_DIM + h * D_HEAD;

    // Q hi -> buf0 (32 KB, transient)
    {
        const __half* gqh = qkvh + (size_t)q0 * E3 + h * D_HEAD;
#pragma unroll
        for (int i = 0; i < 8; i++) {
            int id = tid + i * 256;
            int r = id >> 4;
            int c = id & 15;
            cp_async16(sw_addr(sb, r, c), gqh + (size_t)r * E3 + c * 8);
        }
        cp_commit();
    }
    // k-tile 0 -> buf1
    att_load_tile(sb + ATT_STAGE,         gKh, 0, tid);
    att_load_tile(sb + ATT_STAGE + 16384, gVh, 0, tid);
    cp_commit();

    cp_wait1();            // Q ready (k0 may be in flight)
    __syncthreads();

    uint32_t qh_f[8][4];
    {
        int r = wid * 16 + (lane & 15);
#pragma unroll
        for (int kf = 0; kf < 8; kf++) {
            int c = 2 * kf + (lane >> 4);
            ldm_x4(qh_f[kf], sw_addr(sb, r, c));
        }
    }
    __syncthreads();       // all warps done with Q region (buf0 reusable)

    // k-tile 1 -> buf2
    att_load_tile(sb + 2 * ATT_STAGE,         gKh, 64, tid);
    att_load_tile(sb + 2 * ATT_STAGE + 16384, gVh, 64, tid);
    cp_commit();

    float mA = -INFINITY, mB = -INFINITY, lA = 0.f, lB = 0.f;
    float ctx[16][4];
#pragma unroll
    for (int i = 0; i < 16; i++)
#pragma unroll
        for (int j = 0; j < 4; j++) ctx[i][j] = 0.f;

    const float SCALE = 0.088388347648318447f;
    const float LOG2E = 1.4426950408889634f;
    const int rA = q0 + wid * 16 + (lane >> 2);
    const int rB = rA + 8;
    const int cb = 2 * (lane & 3);

    const int s_br = (lane & 7) + ((lane >> 4) & 1) * 8;
    const int s_bc = (lane >> 3) & 1;
    const int a_r = (lane & 15);
    const int a_c = (lane >> 4);

    for (int kt = 0; kt < ATT_NT; kt++) {
        if (kt < ATT_NT - 2) cp_wait1(); else cp_wait0();
        __syncthreads();
        // tile kt lives in buffer (kt+1)%3
        const uint32_t buf = sb + (uint32_t)(((kt + 1) % 3)) * ATT_STAGE;
        const int k0 = kt * 64;

        // ---- S = scale * Qh @ Kh^T + bias (1-pass)
        float sacc[8][4];
#pragma unroll
        for (int i = 0; i < 8; i++)
#pragma unroll
            for (int j = 0; j < 4; j++) sacc[i][j] = 0.f;

#pragma unroll
        for (int kf = 0; kf < 8; kf++) {
#pragma unroll
            for (int ng = 0; ng < 4; ng++) {
                int r = ng * 16 + s_br;
                int c = 2 * kf + s_bc;
                uint32_t th[4];
                ldm_x4(th, sw_addr(buf, r, c));
                uint32_t b0[2] = {th[0], th[1]}, b1[2] = {th[2], th[3]};
                mma_f16(sacc[2 * ng],     qh_f[kf], b0);
                mma_f16(sacc[2 * ng + 1], qh_f[kf], b1);
            }
        }

        float mxA = -INFINITY, mxB = -INFINITY;
#pragma unroll
        for (int nt = 0; nt < 8; nt++) {
            float2 bA = *(const float2*)(biasM + (size_t)rA * L_SEQ + k0 + nt * 8 + cb);
            float2 bB = *(const float2*)(biasM + (size_t)rB * L_SEQ + k0 + nt * 8 + cb);
            sacc[nt][0] = fmaf(sacc[nt][0], SCALE, bA.x);
            sacc[nt][1] = fmaf(sacc[nt][1], SCALE, bA.y);
            sacc[nt][2] = fmaf(sacc[nt][2], SCALE, bB.x);
            sacc[nt][3] = fmaf(sacc[nt][3], SCALE, bB.y);
            mxA = fmaxf(mxA, fmaxf(sacc[nt][0], sacc[nt][1]));
            mxB = fmaxf(mxB, fmaxf(sacc[nt][2], sacc[nt][3]));
        }
        mxA = fmaxf(mxA, __shfl_xor_sync(0xffffffffu, mxA, 1));
        mxA = fmaxf(mxA, __shfl_xor_sync(0xffffffffu, mxA, 2));
        mxB = fmaxf(mxB, __shfl_xor_sync(0xffffffffu, mxB, 1));
        mxB = fmaxf(mxB, __shfl_xor_sync(0xffffffffu, mxB, 2));
        float mnA = fmaxf(mA, mxA), mnB = fmaxf(mB, mxB);
        float alA = exp2p((mA - mnA) * LOG2E);
        float alB = exp2p((mB - mnB) * LOG2E);
        float negA = mnA * LOG2E, negB = mnB * LOG2E;
        float sumA = 0.f, sumB = 0.f;
#pragma unroll
        for (int nt = 0; nt < 8; nt++) {
            sacc[nt][0] = exp2p(fmaf(sacc[nt][0], LOG2E, -negA));
            sacc[nt][1] = exp2p(fmaf(sacc[nt][1], LOG2E, -negA));
            sacc[nt][2] = exp2p(fmaf(sacc[nt][2], LOG2E, -negB));
            sacc[nt][3] = exp2p(fmaf(sacc[nt][3], LOG2E, -negB));
            sumA += sacc[nt][0] + sacc[nt][1];
            sumB += sacc[nt][2] + sacc[nt][3];
        }
        sumA += __shfl_xor_sync(0xffffffffu, sumA, 1);
        sumA += __shfl_xor_sync(0xffffffffu, sumA, 2);
        sumB += __shfl_xor_sync(0xffffffffu, sumB, 1);
        sumB += __shfl_xor_sync(0xffffffffu, sumB, 2);
        lA = lA * alA + sumA;
        lB = lB * alB + sumB;
        mA = mnA; mB = mnB;
#pragma unroll
        for (int nt = 0; nt < 16; nt++) {
            ctx[nt][0] *= alA; ctx[nt][1] *= alA;
            ctx[nt][2] *= alB; ctx[nt][3] *= alB;
        }

        // ---- P fragments (single fp16 rounding)
        uint32_t pah[4][4];
#pragma unroll
        for (int kb = 0; kb < 4; kb++) {
#pragma unroll
            for (int half = 0; half < 2; half++) {
#pragma unroll
                for (int sub = 0; sub < 2; sub++) {
                    float p0 = sacc[2 * kb + sub][2 * half + 0];
                    float p1 = sacc[2 * kb + sub][2 * half + 1];
                    pah[kb][sub * 2 + half] =
                        pack_h2(__float2half_rn(p0), __float2half_rn(p1));
                }
            }
        }

        // ---- ctx += Ph @ Vh (1-pass), V via ldmatrix.trans
#pragma unroll
        for (int kb = 0; kb < 4; kb++) {
#pragma unroll
            for (int db = 0; db < 8; db++) {
                int r = kb * 16 + a_r;
                int c = 2 * db + a_c;
                uint32_t th[4];
                ldm_x4_t(th, sw_addr(buf + 16384, r, c));
                uint32_t b0[2] = {th[0], th[1]}, b1[2] = {th[2], th[3]};
                mma_f16(ctx[2 * db],     pah[kb], b0);
                mma_f16(ctx[2 * db + 1], pah[kb], b1);
            }
        }

        __syncthreads();
        if (kt + 2 < ATT_NT) {
            const uint32_t nbuf = sb + (uint32_t)((kt % 3)) * ATT_STAGE;
            const int nk0 = (kt + 2) * 64;
            att_load_tile(nbuf + 0,     gKh, nk0, tid);
            att_load_tile(nbuf + 16384, gVh, nk0, tid);
            cp_commit();
        } else {
            cp_commit();
        }
    }

    // ---- epilogue: normalize, round to fp16, write ctx
    float iA = 1.f / lA, iB = 1.f / lB;
#pragma unroll
    for (int nt = 0; nt < 16; nt++) {
        int col = h * D_HEAD + nt * 8 + cb;
        float v0 = ctx[nt][0] * iA, v1 = ctx[nt][1] * iA;
        float v2 = ctx[nt][2] * iB, v3 = ctx[nt][3] * iB;
        *(uint32_t*)(ch + (size_t)rA * E_DIM + col) =
            pack_h2(__float2half_rn(v0), __float2half_rn(v1));
        *(uint32_t*)(ch + (size_t)rB * E_DIM + col) =
            pack_h2(__float2half_rn(v2), __float2half_rn(v3));
    }
}

// ---------------------------------------------------------------------------
extern "C" void kernel_launch(void* const* d_in, const int* in_sizes, int n_in,
                              void* d_out, int out_size)
{
    const float* x     = (const float*)d_in[0];
    const float* biasM = (const float*)d_in[1];
    const float* w_in  = (const float*)d_in[2];
    const float* b_in  = (const float*)d_in[3];
    const float* w_out = (const float*)d_in[4];
    const float* b_out = (const float*)d_in[5];
    float* out = (float*)d_out;

    __half *xh, *wih, *woh, *qkvh, *ch;
    cudaGetSymbolAddress((void**)&xh, g_xh);
    cudaGetSymbolAddress((void**)&wih, g_wih);
    cudaGetSymbolAddress((void**)&woh, g_woh);
    cudaGetSymbolAddress((void**)&qkvh, g_qkvh);
    cudaGetSymbolAddress((void**)&ch, g_ch);

    cudaFuncSetAttribute(gemm_mma, cudaFuncAttributeMaxDynamicSharedMemorySize, GM_SMEM);
    cudaFuncSetAttribute(attn_tc, cudaFuncAttributeMaxDynamicSharedMemorySize, ATT_SMEM);

    {
        int n4 = (L_SEQ * E_DIM) / 4;
        conv_f16_kernel<<<(n4 + 255) / 256, 256>>>(x, xh, n4);
        int w4 = (E3 * E_DIM) / 4;
        conv_f16_kernel<<<(w4 + 255) / 256, 256>>>(w_in, wih, w4);
        int o4 = (E_DIM * E_DIM) / 4;
        conv_f16_kernel<<<(o4 + 255) / 256, 256>>>(w_out, woh, o4);
    }

    // 1) QKV projection -> fp16   [2048, 6144]
    gemm_mma<<<dim3(E3 / 128, L_SEQ / 128), 256, GM_SMEM>>>(
        xh, wih, b_in, nullptr, qkvh, L_SEQ, E3, E_DIM);

    // 2) fp16 1-pass tensor-core attention -> fp16 ctx
    attn_tc<<<dim3(L_SEQ / 128, H_NUM), 256, ATT_SMEM>>>(
        qkvh, biasM, ch);

    // 3) out projection -> fp32 output   [2048, 2048]
    gemm_mma<<<dim3(E_DIM / 128, L_SEQ / 128), 256, GM_SMEM>>>(
        ch, woh, b_out, out, nullptr, L_SEQ, E_DIM, E_DIM);
}

// round 12
// speedup vs baseline: 2.1592x; 1.0307x over previous
#include <cuda_runtime.h>
#include <cuda_fp16.h>
#include <cstdint>
#include <math.h>

#define L_SEQ 2048
#define E_DIM 2048
#define H_NUM 16
#define D_HEAD 128
#define E3 6144

// ---------------------------------------------------------------------------
// Device-global scratch (allocation-free rule)
// ---------------------------------------------------------------------------
__device__ __align__(16) __half g_xh[L_SEQ * E_DIM];
__device__ __align__(16) __half g_wih[E3 * E_DIM];
__device__ __align__(16) __half g_woh[E_DIM * E_DIM];
__device__ __align__(16) __half g_qkvh[L_SEQ * E3];
__device__ __align__(16) __half g_ch[L_SEQ * E_DIM];

__device__ __forceinline__ uint32_t smem_u32(const void* p) {
    uint32_t a;
    asm("{ .reg .u64 t; cvta.to.shared.u64 t, %1; cvt.u32.u64 %0, t; }" : "=r"(a) : "l"(p));
    return a;
}
__device__ __forceinline__ void cp_async16(uint32_t dst, const void* src) {
    asm volatile("cp.async.cg.shared.global [%0], [%1], 16;" :: "r"(dst), "l"(src));
}
__device__ __forceinline__ void cp_commit() {
    asm volatile("cp.async.commit_group;" ::: "memory");
}
__device__ __forceinline__ void cp_wait2() {
    asm volatile("cp.async.wait_group 2;" ::: "memory");
}
__device__ __forceinline__ void cp_wait1() {
    asm volatile("cp.async.wait_group 1;" ::: "memory");
}
__device__ __forceinline__ void cp_wait0() {
    asm volatile("cp.async.wait_group 0;" ::: "memory");
}
__device__ __forceinline__ void ldm_x4(uint32_t* r, uint32_t addr) {
    asm volatile("ldmatrix.sync.aligned.m8n8.x4.shared.b16 {%0,%1,%2,%3}, [%4];"
                 : "=r"(r[0]), "=r"(r[1]), "=r"(r[2]), "=r"(r[3]) : "r"(addr));
}
__device__ __forceinline__ void ldm_x4_t(uint32_t* r, uint32_t addr) {
    asm volatile("ldmatrix.sync.aligned.m8n8.x4.trans.shared.b16 {%0,%1,%2,%3}, [%4];"
                 : "=r"(r[0]), "=r"(r[1]), "=r"(r[2]), "=r"(r[3]) : "r"(addr));
}
__device__ __forceinline__ void mma_f16(float* c, const uint32_t* a, const uint32_t* b) {
    asm("mma.sync.aligned.m16n8k16.row.col.f32.f16.f16.f32 "
        "{%0,%1,%2,%3}, {%4,%5,%6,%7}, {%8,%9}, {%0,%1,%2,%3};"
        : "+f"(c[0]), "+f"(c[1]), "+f"(c[2]), "+f"(c[3])
        : "r"(a[0]), "r"(a[1]), "r"(a[2]), "r"(a[3]), "r"(b[0]), "r"(b[1]));
}
__device__ __forceinline__ uint32_t pack_h2(__half a, __half b) {
    __half2 t = __halves2half2(a, b);
    return *reinterpret_cast<uint32_t*>(&t);
}
// Hardware exp2 on the MUFU pipe (overlaps with FMA and tensor pipes).
// ex2.approx(-inf) = +0, which preserves online-softmax init semantics.
__device__ __forceinline__ float ex2(float x) {
    float y;
    asm("ex2.approx.f32 %0, %1;" : "=f"(y) : "f"(x));
    return y;
}

// ---------------------------------------------------------------------------
// fp32 -> fp16 convert
// ---------------------------------------------------------------------------
__global__ void conv_f16_kernel(const float* __restrict__ in,
                                __half* __restrict__ hi, int n4)
{
    int i = blockIdx.x * blockDim.x + threadIdx.x;
    if (i >= n4) return;
    float4 v = ((const float4*)in)[i];
    ((__half2*)hi)[2 * i]     = __halves2half2(__float2half_rn(v.x), __float2half_rn(v.y));
    ((__half2*)hi)[2 * i + 1] = __halves2half2(__float2half_rn(v.z), __float2half_rn(v.w));
}

// ---------------------------------------------------------------------------
// fp16 1-pass GEMM: C = A @ B^T + bias.
// CTA 128x128, 8 warps of 64x32, 4-stage ring (16KB/stage), 2 CTAs/SM.
// ---------------------------------------------------------------------------
#define GM_TILE_BYTES 8192
#define GM_STAGE (2 * GM_TILE_BYTES)       // A, B = 16 KB
#define GM_NSTAGE 4
#define GM_SMEM (GM_NSTAGE * GM_STAGE)     // 64 KB per CTA

__device__ __forceinline__ void issue_tile(uint32_t smem_tile,
                                           const __half* __restrict__ G,
                                           int row0, int k0, int K, int tid)
{
#pragma unroll
    for (int t = 0; t < 2; t++) {
        int id = tid + t * 256;
        int r  = id >> 2;
        int c  = id & 3;
        int pc = c ^ ((r >> 1) & 3);
        cp_async16(smem_tile + r * 64 + pc * 16,
                   G + (size_t)(row0 + r) * K + k0 + c * 8);
    }
}
__device__ __forceinline__ void issue_stage(uint32_t base,
                                            const __half* A, const __half* B,
                                            int m0, int n0, int k0, int K, int tid)
{
    issue_tile(base,                 A, m0, k0, K, tid);
    issue_tile(base + GM_TILE_BYTES, B, n0, k0, K, tid);
}

__global__ __launch_bounds__(256, 2) void gemm_mma(
    const __half* __restrict__ A, const __half* __restrict__ B,
    const float* __restrict__ bias, float* __restrict__ Cf,
    __half* __restrict__ Ch,
    int M, int N, int K)
{
    extern __shared__ char smc[];
    const uint32_t sb = smem_u32(smc);
    const int tid = threadIdx.x;
    const int lane = tid & 31;
    const int wid = tid >> 5;
    const int wm = wid & 1;
    const int wn = wid >> 1;
    const int m0 = blockIdx.y * 128;
    const int n0 = blockIdx.x * 128;

    const int S = K >> 5;

#pragma unroll
    for (int s = 0; s < 3; s++) {
        issue_stage(sb + s * GM_STAGE, A, B, m0, n0, s * 32, K, tid);
        cp_commit();
    }

    float acc[4][4][4];
#pragma unroll
    for (int i = 0; i < 4; i++)
#pragma unroll
        for (int j = 0; j < 4; j++)
#pragma unroll
            for (int r = 0; r < 4; r++) acc[i][j][r] = 0.f;

    const int a_r = wm * 64 + (lane & 15);
    const int a_c = (lane >> 4);
    const int b_sub = lane >> 3;
    const int b_r = wn * 32 + (lane & 7) + (b_sub >> 1) * 8;
    const int b_c = (b_sub & 1);

    for (int s = 0; s < S; s++) {
        cp_wait2();
        __syncthreads();

        if (s + 3 < S)
            issue_stage(sb + ((s + 3) & 3) * GM_STAGE, A, B,
                        m0, n0, (s + 3) * 32, K, tid);
        cp_commit();

        const uint32_t base = sb + (s & 3) * GM_STAGE;
        const uint32_t tA = base;
        const uint32_t tB = base + GM_TILE_BYTES;

#pragma unroll
        for (int ks = 0; ks < 2; ks++) {
            uint32_t ah[4][4], bh[4][2];
#pragma unroll
            for (int mt = 0; mt < 4; mt++) {
                int r = a_r + mt * 16;
                int pc = (ks * 2 + a_c) ^ ((r >> 1) & 3);
                ldm_x4(ah[mt], tA + r * 64 + pc * 16);
            }
#pragma unroll
            for (int g = 0; g < 2; g++) {
                int r = b_r + g * 16;
                int pc = (ks * 2 + b_c) ^ ((r >> 1) & 3);
                uint32_t th[4];
                ldm_x4(th, tB + r * 64 + pc * 16);
                bh[g * 2][0] = th[0]; bh[g * 2][1] = th[1];
                bh[g * 2 + 1][0] = th[2]; bh[g * 2 + 1][1] = th[3];
            }
#pragma unroll
            for (int mt = 0; mt < 4; mt++)
#pragma unroll
                for (int nt = 0; nt < 4; nt++)
                    mma_f16(acc[mt][nt], ah[mt], bh[nt]);
        }
    }

    const int cm = m0 + wm * 64 + (lane >> 2);
    const int cn = n0 + wn * 32 + (lane & 3) * 2;
    if (Cf) {
#pragma unroll
        for (int nt = 0; nt < 4; nt++) {
            float b0 = bias[cn + nt * 8];
            float b1 = bias[cn + nt * 8 + 1];
#pragma unroll
            for (int mt = 0; mt < 4; mt++) {
                float* r0 = Cf + (size_t)(cm + mt * 16) * N + cn + nt * 8;
                float* r1 = r0 + 8 * N;
                *(float2*)r0 = make_float2(acc[mt][nt][0] + b0, acc[mt][nt][1] + b1);
                *(float2*)r1 = make_float2(acc[mt][nt][2] + b0, acc[mt][nt][3] + b1);
            }
        }
    } else {
#pragma unroll
        for (int nt = 0; nt < 4; nt++) {
            float b0 = bias[cn + nt * 8];
            float b1 = bias[cn + nt * 8 + 1];
#pragma unroll
            for (int mt = 0; mt < 4; mt++) {
#pragma unroll
                for (int half = 0; half < 2; half++) {
                    float v0 = acc[mt][nt][2 * half + 0] + b0;
                    float v1 = acc[mt][nt][2 * half + 1] + b1;
                    size_t off = (size_t)(cm + mt * 16 + half * 8) * N + cn + nt * 8;
                    *(uint32_t*)(Ch + off) =
                        pack_h2(__float2half_rn(v0), __float2half_rn(v1));
                }
            }
        }
    }
}

// ---------------------------------------------------------------------------
// fp16 1-pass tensor-core flash attention: S = Qh@Kh^T ; ctx = Ph@Vh.
// 3-buffer ring of 32KB K/V stages; Q (hi only) transient in buf0.
// Softmax exp on MUFU (ex2.approx) to unload the FMA pipe.
// ---------------------------------------------------------------------------
#define ATT_STAGE 32768                  // Kh 16K + Vh 16K
#define ATT_SMEM (3 * ATT_STAGE)         // 96 KB
#define ATT_NT 32

__device__ __forceinline__ uint32_t sw_addr(uint32_t base, int r, int c) {
    return base + r * 256 + ((c ^ (r & 7)) << 4);
}
__device__ __forceinline__ void att_load_tile(uint32_t dst,
                                              const __half* __restrict__ g,
                                              int k0, int tid)
{
#pragma unroll
    for (int i = 0; i < 4; i++) {
        int id = tid + i * 256;
        int r = id >> 4;
        int c = id & 15;
        cp_async16(sw_addr(dst, r, c), g + (size_t)(k0 + r) * E3 + c * 8);
    }
}

__global__ __launch_bounds__(256, 1) void attn_tc(
    const __half* __restrict__ qkvh,
    const float* __restrict__ biasM,
    __half* __restrict__ ch)
{
    extern __shared__ char smc[];
    const uint32_t sb = smem_u32(smc);
    const int tid = threadIdx.x;
    const int lane = tid & 31;
    const int wid = tid >> 5;
    const int h = blockIdx.y;
    const int q0 = blockIdx.x * 128;

    const __half* gKh = qkvh + E_DIM + h * D_HEAD;
    const __half* gVh = qkvh + 2 * E_DIM + h * D_HEAD;

    // Q hi -> buf0 (32 KB, transient)
    {
        const __half* gqh = qkvh + (size_t)q0 * E3 + h * D_HEAD;
#pragma unroll
        for (int i = 0; i < 8; i++) {
            int id = tid + i * 256;
            int r = id >> 4;
            int c = id & 15;
            cp_async16(sw_addr(sb, r, c), gqh + (size_t)r * E3 + c * 8);
        }
        cp_commit();
    }
    // k-tile 0 -> buf1
    att_load_tile(sb + ATT_STAGE,         gKh, 0, tid);
    att_load_tile(sb + ATT_STAGE + 16384, gVh, 0, tid);
    cp_commit();

    cp_wait1();            // Q ready (k0 may be in flight)
    __syncthreads();

    uint32_t qh_f[8][4];
    {
        int r = wid * 16 + (lane & 15);
#pragma unroll
        for (int kf = 0; kf < 8; kf++) {
            int c = 2 * kf + (lane >> 4);
            ldm_x4(qh_f[kf], sw_addr(sb, r, c));
        }
    }
    __syncthreads();       // all warps done with Q region (buf0 reusable)

    // k-tile 1 -> buf2
    att_load_tile(sb + 2 * ATT_STAGE,         gKh, 64, tid);
    att_load_tile(sb + 2 * ATT_STAGE + 16384, gVh, 64, tid);
    cp_commit();

    float mA = -INFINITY, mB = -INFINITY, lA = 0.f, lB = 0.f;
    float ctx[16][4];
#pragma unroll
    for (int i = 0; i < 16; i++)
#pragma unroll
        for (int j = 0; j < 4; j++) ctx[i][j] = 0.f;

    const float SCALE = 0.088388347648318447f;
    const float LOG2E = 1.4426950408889634f;
    const int rA = q0 + wid * 16 + (lane >> 2);
    const int rB = rA + 8;
    const int cb = 2 * (lane & 3);

    const int s_br = (lane & 7) + ((lane >> 4) & 1) * 8;
    const int s_bc = (lane >> 3) & 1;
    const int a_r = (lane & 15);
    const int a_c = (lane >> 4);

    for (int kt = 0; kt < ATT_NT; kt++) {
        if (kt < ATT_NT - 2) cp_wait1(); else cp_wait0();
        __syncthreads();
        // tile kt lives in buffer (kt+1)%3
        const uint32_t buf = sb + (uint32_t)(((kt + 1) % 3)) * ATT_STAGE;
        const int k0 = kt * 64;

        // ---- S = scale * Qh @ Kh^T + bias (1-pass)
        float sacc[8][4];
#pragma unroll
        for (int i = 0; i < 8; i++)
#pragma unroll
            for (int j = 0; j < 4; j++) sacc[i][j] = 0.f;

#pragma unroll
        for (int kf = 0; kf < 8; kf++) {
#pragma unroll
            for (int ng = 0; ng < 4; ng++) {
                int r = ng * 16 + s_br;
                int c = 2 * kf + s_bc;
                uint32_t th[4];
                ldm_x4(th, sw_addr(buf, r, c));
                uint32_t b0[2] = {th[0], th[1]}, b1[2] = {th[2], th[3]};
                mma_f16(sacc[2 * ng],     qh_f[kf], b0);
                mma_f16(sacc[2 * ng + 1], qh_f[kf], b1);
            }
        }

        float mxA = -INFINITY, mxB = -INFINITY;
#pragma unroll
        for (int nt = 0; nt < 8; nt++) {
            float2 bA = *(const float2*)(biasM + (size_t)rA * L_SEQ + k0 + nt * 8 + cb);
            float2 bB = *(const float2*)(biasM + (size_t)rB * L_SEQ + k0 + nt * 8 + cb);
            sacc[nt][0] = fmaf(sacc[nt][0], SCALE, bA.x);
            sacc[nt][1] = fmaf(sacc[nt][1], SCALE, bA.y);
            sacc[nt][2] = fmaf(sacc[nt][2], SCALE, bB.x);
            sacc[nt][3] = fmaf(sacc[nt][3], SCALE, bB.y);
            mxA = fmaxf(mxA, fmaxf(sacc[nt][0], sacc[nt][1]));
            mxB = fmaxf(mxB, fmaxf(sacc[nt][2], sacc[nt][3]));
        }
        mxA = fmaxf(mxA, __shfl_xor_sync(0xffffffffu, mxA, 1));
        mxA = fmaxf(mxA, __shfl_xor_sync(0xffffffffu, mxA, 2));
        mxB = fmaxf(mxB, __shfl_xor_sync(0xffffffffu, mxB, 1));
        mxB = fmaxf(mxB, __shfl_xor_sync(0xffffffffu, mxB, 2));
        float mnA = fmaxf(mA, mxA), mnB = fmaxf(mB, mxB);
        float alA = ex2((mA - mnA) * LOG2E);
        float alB = ex2((mB - mnB) * LOG2E);
        float negA = mnA * LOG2E, negB = mnB * LOG2E;
        float sumA = 0.f, sumB = 0.f;
#pragma unroll
        for (int nt = 0; nt < 8; nt++) {
            sacc[nt][0] = ex2(fmaf(sacc[nt][0], LOG2E, -negA));
            sacc[nt][1] = ex2(fmaf(sacc[nt][1], LOG2E, -negA));
            sacc[nt][2] = ex2(fmaf(sacc[nt][2], LOG2E, -negB));
            sacc[nt][3] = ex2(fmaf(sacc[nt][3], LOG2E, -negB));
            sumA += sacc[nt][0] + sacc[nt][1];
            sumB += sacc[nt][2] + sacc[nt][3];
        }
        sumA += __shfl_xor_sync(0xffffffffu, sumA, 1);
        sumA += __shfl_xor_sync(0xffffffffu, sumA, 2);
        sumB += __shfl_xor_sync(0xffffffffu, sumB, 1);
        sumB += __shfl_xor_sync(0xffffffffu, sumB, 2);
        lA = lA * alA + sumA;
        lB = lB * alB + sumB;
        mA = mnA; mB = mnB;
#pragma unroll
        for (int nt = 0; nt < 16; nt++) {
            ctx[nt][0] *= alA; ctx[nt][1] *= alA;
            ctx[nt][2] *= alB; ctx[nt][3] *= alB;
        }

        // ---- P fragments (single fp16 rounding)
        uint32_t pah[4][4];
#pragma unroll
        for (int kb = 0; kb < 4; kb++) {
#pragma unroll
            for (int half = 0; half < 2; half++) {
#pragma unroll
                for (int sub = 0; sub < 2; sub++) {
                    float p0 = sacc[2 * kb + sub][2 * half + 0];
                    float p1 = sacc[2 * kb + sub][2 * half + 1];
                    pah[kb][sub * 2 + half] =
                        pack_h2(__float2half_rn(p0), __float2half_rn(p1));
                }
            }
        }

        // ---- ctx += Ph @ Vh (1-pass), V via ldmatrix.trans
#pragma unroll
        for (int kb = 0; kb < 4; kb++) {
#pragma unroll
            for (int db = 0; db < 8; db++) {
                int r = kb * 16 + a_r;
                int c = 2 * db + a_c;
                uint32_t th[4];
                ldm_x4_t(th, sw_addr(buf + 16384, r, c));
                uint32_t b0[2] = {th[0], th[1]}, b1[2] = {th[2], th[3]};
                mma_f16(ctx[2 * db],     pah[kb], b0);
                mma_f16(ctx[2 * db + 1], pah[kb], b1);
            }
        }

        __syncthreads();
        if (kt + 2 < ATT_NT) {
            const uint32_t nbuf = sb + (uint32_t)((kt % 3)) * ATT_STAGE;
            const int nk0 = (kt + 2) * 64;
            att_load_tile(nbuf + 0,     gKh, nk0, tid);
            att_load_tile(nbuf + 16384, gVh, nk0, tid);
            cp_commit();
        } else {
            cp_commit();
        }
    }

    // ---- epilogue: normalize, round to fp16, write ctx
    float iA = 1.f / lA, iB = 1.f / lB;
#pragma unroll
    for (int nt = 0; nt < 16; nt++) {
        int col = h * D_HEAD + nt * 8 + cb;
        float v0 = ctx[nt][0] * iA, v1 = ctx[nt][1] * iA;
        float v2 = ctx[nt][2] * iB, v3 = ctx[nt][3] * iB;
        *(uint32_t*)(ch + (size_t)rA * E_DIM + col) =
            pack_h2(__float2half_rn(v0), __float2half_rn(v1));
        *(uint32_t*)(ch + (size_t)rB * E_DIM + col) =
            pack_h2(__float2half_rn(v2), __float2half_rn(v3));
    }
}

// ---------------------------------------------------------------------------
extern "C" void kernel_launch(void* const* d_in, const int* in_sizes, int n_in,
                              void* d_out, int out_size)
{
    const float* x     = (const float*)d_in[0];
    const float* biasM = (const float*)d_in[1];
    const float* w_in  = (const float*)d_in[2];
    const float* b_in  = (const float*)d_in[3];
    const float* w_out = (const float*)d_in[4];
    const float* b_out = (const float*)d_in[5];
    float* out = (float*)d_out;

    __half *xh, *wih, *woh, *qkvh, *ch;
    cudaGetSymbolAddress((void**)&xh, g_xh);
    cudaGetSymbolAddress((void**)&wih, g_wih);
    cudaGetSymbolAddress((void**)&woh, g_woh);
    cudaGetSymbolAddress((void**)&qkvh, g_qkvh);
    cudaGetSymbolAddress((void**)&ch, g_ch);

    cudaFuncSetAttribute(gemm_mma, cudaFuncAttributeMaxDynamicSharedMemorySize, GM_SMEM);
    cudaFuncSetAttribute(attn_tc, cudaFuncAttributeMaxDynamicSharedMemorySize, ATT_SMEM);

    {
        int n4 = (L_SEQ * E_DIM) / 4;
        conv_f16_kernel<<<(n4 + 255) / 256, 256>>>(x, xh, n4);
        int w4 = (E3 * E_DIM) / 4;
        conv_f16_kernel<<<(w4 + 255) / 256, 256>>>(w_in, wih, w4);
        int o4 = (E_DIM * E_DIM) / 4;
        conv_f16_kernel<<<(o4 + 255) / 256, 256>>>(w_out, woh, o4);
    }

    // 1) QKV projection -> fp16   [2048, 6144]
    gemm_mma<<<dim3(E3 / 128, L_SEQ / 128), 256, GM_SMEM>>>(
        xh, wih, b_in, nullptr, qkvh, L_SEQ, E3, E_DIM);

    // 2) fp16 1-pass tensor-core attention -> fp16 ctx
    attn_tc<<<dim3(L_SEQ / 128, H_NUM), 256, ATT_SMEM>>>(
        qkvh, biasM, ch);

    // 3) out projection -> fp32 output   [2048, 2048]
    gemm_mma<<<dim3(E_DIM / 128, L_SEQ / 128), 256, GM_SMEM>>>(
        ch, woh, b_out, out, nullptr, L_SEQ, E_DIM, E_DIM);
}

// round 13
// speedup vs baseline: 2.3191x; 1.0740x over previous
#include <cuda_runtime.h>
#include <cuda_fp16.h>
#include <cstdint>
#include <math.h>

#define L_SEQ 2048
#define E_DIM 2048
#define H_NUM 16
#define D_HEAD 128
#define E3 6144

// ---------------------------------------------------------------------------
// Device-global scratch (allocation-free rule)
// ---------------------------------------------------------------------------
__device__ __align__(16) __half g_xh[L_SEQ * E_DIM];
__device__ __align__(16) __half g_wih[E3 * E_DIM];
__device__ __align__(16) __half g_woh[E_DIM * E_DIM];
__device__ __align__(16) __half g_qkvh[L_SEQ * E3];
__device__ __align__(16) __half g_ch[L_SEQ * E_DIM];

__device__ __forceinline__ uint32_t smem_u32(const void* p) {
    uint32_t a;
    asm("{ .reg .u64 t; cvta.to.shared.u64 t, %1; cvt.u32.u64 %0, t; }" : "=r"(a) : "l"(p));
    return a;
}
__device__ __forceinline__ void cp_async16(uint32_t dst, const void* src) {
    asm volatile("cp.async.cg.shared.global [%0], [%1], 16;" :: "r"(dst), "l"(src));
}
__device__ __forceinline__ void cp_commit() {
    asm volatile("cp.async.commit_group;" ::: "memory");
}
__device__ __forceinline__ void cp_wait2() {
    asm volatile("cp.async.wait_group 2;" ::: "memory");
}
__device__ __forceinline__ void cp_wait1() {
    asm volatile("cp.async.wait_group 1;" ::: "memory");
}
__device__ __forceinline__ void cp_wait0() {
    asm volatile("cp.async.wait_group 0;" ::: "memory");
}
__device__ __forceinline__ void ldm_x4(uint32_t* r, uint32_t addr) {
    asm volatile("ldmatrix.sync.aligned.m8n8.x4.shared.b16 {%0,%1,%2,%3}, [%4];"
                 : "=r"(r[0]), "=r"(r[1]), "=r"(r[2]), "=r"(r[3]) : "r"(addr));
}
__device__ __forceinline__ void ldm_x4_t(uint32_t* r, uint32_t addr) {
    asm volatile("ldmatrix.sync.aligned.m8n8.x4.trans.shared.b16 {%0,%1,%2,%3}, [%4];"
                 : "=r"(r[0]), "=r"(r[1]), "=r"(r[2]), "=r"(r[3]) : "r"(addr));
}
__device__ __forceinline__ void mma_f16(float* c, const uint32_t* a, const uint32_t* b) {
    asm("mma.sync.aligned.m16n8k16.row.col.f32.f16.f16.f32 "
        "{%0,%1,%2,%3}, {%4,%5,%6,%7}, {%8,%9}, {%0,%1,%2,%3};"
        : "+f"(c[0]), "+f"(c[1]), "+f"(c[2]), "+f"(c[3])
        : "r"(a[0]), "r"(a[1]), "r"(a[2]), "r"(a[3]), "r"(b[0]), "r"(b[1]));
}
__device__ __forceinline__ uint32_t pack_h2(__half a, __half b) {
    __half2 t = __halves2half2(a, b);
    return *reinterpret_cast<uint32_t*>(&t);
}
// Hardware exp2 on the MUFU pipe. ex2.approx(-inf) = +0.
__device__ __forceinline__ float ex2(float x) {
    float y;
    asm("ex2.approx.f32 %0, %1;" : "=f"(y) : "f"(x));
    return y;
}

// ---------------------------------------------------------------------------
// fp32 -> fp16 convert
// ---------------------------------------------------------------------------
__global__ void conv_f16_kernel(const float* __restrict__ in,
                                __half* __restrict__ hi, int n4)
{
    int i = blockIdx.x * blockDim.x + threadIdx.x;
    if (i >= n4) return;
    float4 v = ((const float4*)in)[i];
    ((__half2*)hi)[2 * i]     = __halves2half2(__float2half_rn(v.x), __float2half_rn(v.y));
    ((__half2*)hi)[2 * i + 1] = __halves2half2(__float2half_rn(v.z), __float2half_rn(v.w));
}

// ---------------------------------------------------------------------------
// fp16 1-pass GEMM: C = A @ B^T + bias.  (unchanged from R12)
// CTA 128x128, 8 warps of 64x32, 4-stage ring (16KB/stage), 2 CTAs/SM.
// ---------------------------------------------------------------------------
#define GM_TILE_BYTES 8192
#define GM_STAGE (2 * GM_TILE_BYTES)
#define GM_NSTAGE 4
#define GM_SMEM (GM_NSTAGE * GM_STAGE)     // 64 KB per CTA

__device__ __forceinline__ void issue_tile(uint32_t smem_tile,
                                           const __half* __restrict__ G,
                                           int row0, int k0, int K, int tid)
{
#pragma unroll
    for (int t = 0; t < 2; t++) {
        int id = tid + t * 256;
        int r  = id >> 2;
        int c  = id & 3;
        int pc = c ^ ((r >> 1) & 3);
        cp_async16(smem_tile + r * 64 + pc * 16,
                   G + (size_t)(row0 + r) * K + k0 + c * 8);
    }
}
__device__ __forceinline__ void issue_stage(uint32_t base,
                                            const __half* A, const __half* B,
                                            int m0, int n0, int k0, int K, int tid)
{
    issue_tile(base,                 A, m0, k0, K, tid);
    issue_tile(base + GM_TILE_BYTES, B, n0, k0, K, tid);
}

__global__ __launch_bounds__(256, 2) void gemm_mma(
    const __half* __restrict__ A, const __half* __restrict__ B,
    const float* __restrict__ bias, float* __restrict__ Cf,
    __half* __restrict__ Ch,
    int M, int N, int K)
{
    extern __shared__ char smc[];
    const uint32_t sb = smem_u32(smc);
    const int tid = threadIdx.x;
    const int lane = tid & 31;
    const int wid = tid >> 5;
    const int wm = wid & 1;
    const int wn = wid >> 1;
    const int m0 = blockIdx.y * 128;
    const int n0 = blockIdx.x * 128;

    const int S = K >> 5;

#pragma unroll
    for (int s = 0; s < 3; s++) {
        issue_stage(sb + s * GM_STAGE, A, B, m0, n0, s * 32, K, tid);
        cp_commit();
    }

    float acc[4][4][4];
#pragma unroll
    for (int i = 0; i < 4; i++)
#pragma unroll
        for (int j = 0; j < 4; j++)
#pragma unroll
            for (int r = 0; r < 4; r++) acc[i][j][r] = 0.f;

    const int a_r = wm * 64 + (lane & 15);
    const int a_c = (lane >> 4);
    const int b_sub = lane >> 3;
    const int b_r = wn * 32 + (lane & 7) + (b_sub >> 1) * 8;
    const int b_c = (b_sub & 1);

    for (int s = 0; s < S; s++) {
        cp_wait2();
        __syncthreads();

        if (s + 3 < S)
            issue_stage(sb + ((s + 3) & 3) * GM_STAGE, A, B,
                        m0, n0, (s + 3) * 32, K, tid);
        cp_commit();

        const uint32_t base = sb + (s & 3) * GM_STAGE;
        const uint32_t tA = base;
        const uint32_t tB = base + GM_TILE_BYTES;

#pragma unroll
        for (int ks = 0; ks < 2; ks++) {
            uint32_t ah[4][4], bh[4][2];
#pragma unroll
            for (int mt = 0; mt < 4; mt++) {
                int r = a_r + mt * 16;
                int pc = (ks * 2 + a_c) ^ ((r >> 1) & 3);
                ldm_x4(ah[mt], tA + r * 64 + pc * 16);
            }
#pragma unroll
            for (int g = 0; g < 2; g++) {
                int r = b_r + g * 16;
                int pc = (ks * 2 + b_c) ^ ((r >> 1) & 3);
                uint32_t th[4];
                ldm_x4(th, tB + r * 64 + pc * 16);
                bh[g * 2][0] = th[0]; bh[g * 2][1] = th[1];
                bh[g * 2 + 1][0] = th[2]; bh[g * 2 + 1][1] = th[3];
            }
#pragma unroll
            for (int mt = 0; mt < 4; mt++)
#pragma unroll
                for (int nt = 0; nt < 4; nt++)
                    mma_f16(acc[mt][nt], ah[mt], bh[nt]);
        }
    }

    const int cm = m0 + wm * 64 + (lane >> 2);
    const int cn = n0 + wn * 32 + (lane & 3) * 2;
    if (Cf) {
#pragma unroll
        for (int nt = 0; nt < 4; nt++) {
            float b0 = bias[cn + nt * 8];
            float b1 = bias[cn + nt * 8 + 1];
#pragma unroll
            for (int mt = 0; mt < 4; mt++) {
                float* r0 = Cf + (size_t)(cm + mt * 16) * N + cn + nt * 8;
                float* r1 = r0 + 8 * N;
                *(float2*)r0 = make_float2(acc[mt][nt][0] + b0, acc[mt][nt][1] + b1);
                *(float2*)r1 = make_float2(acc[mt][nt][2] + b0, acc[mt][nt][3] + b1);
            }
        }
    } else {
#pragma unroll
        for (int nt = 0; nt < 4; nt++) {
            float b0 = bias[cn + nt * 8];
            float b1 = bias[cn + nt * 8 + 1];
#pragma unroll
            for (int mt = 0; mt < 4; mt++) {
#pragma unroll
                for (int half = 0; half < 2; half++) {
                    float v0 = acc[mt][nt][2 * half + 0] + b0;
                    float v1 = acc[mt][nt][2 * half + 1] + b1;
                    size_t off = (size_t)(cm + mt * 16 + half * 8) * N + cn + nt * 8;
                    *(uint32_t*)(Ch + off) =
                        pack_h2(__float2half_rn(v0), __float2half_rn(v1));
                }
            }
        }
    }
}

// ---------------------------------------------------------------------------
// fp16 1-pass flash attention, BK=128 (one softmax pass per 128 keys).
// 2-stage ring of 64KB stages (K 32K + V 32K); Q transient in buf0.
// ---------------------------------------------------------------------------
#define ATT_BK 128
#define ATT_STAGE 65536                  // Kh 32K + Vh 32K
#define ATT_SMEM (2 * ATT_STAGE)         // 128 KB
#define ATT_NT 16                        // 2048 / 128

__device__ __forceinline__ uint32_t sw_addr(uint32_t base, int r, int c) {
    return base + r * 256 + ((c ^ (r & 7)) << 4);
}
// load a 128-row x 128-col fp16 tile (32 KB)
__device__ __forceinline__ void att_load_tile(uint32_t dst,
                                              const __half* __restrict__ g,
                                              int k0, int tid)
{
#pragma unroll
    for (int i = 0; i < 8; i++) {
        int id = tid + i * 256;
        int r = id >> 4;
        int c = id & 15;
        cp_async16(sw_addr(dst, r, c), g + (size_t)(k0 + r) * E3 + c * 8);
    }
}

__global__ __launch_bounds__(256, 1) void attn_tc(
    const __half* __restrict__ qkvh,
    const float* __restrict__ biasM,
    __half* __restrict__ ch)
{
    extern __shared__ char smc[];
    const uint32_t sb = smem_u32(smc);
    const int tid = threadIdx.x;
    const int lane = tid & 31;
    const int wid = tid >> 5;
    const int h = blockIdx.y;
    const int q0 = blockIdx.x * 128;

    const __half* gKh = qkvh + E_DIM + h * D_HEAD;
    const __half* gVh = qkvh + 2 * E_DIM + h * D_HEAD;

    // Q -> buf0 (32 KB, transient)
    {
        const __half* gqh = qkvh + (size_t)q0 * E3 + h * D_HEAD;
#pragma unroll
        for (int i = 0; i < 8; i++) {
            int id = tid + i * 256;
            int r = id >> 4;
            int c = id & 15;
            cp_async16(sw_addr(sb, r, c), gqh + (size_t)r * E3 + c * 8);
        }
        cp_commit();
    }
    // tile 0 -> buf1
    att_load_tile(sb + ATT_STAGE,         gKh, 0, tid);
    att_load_tile(sb + ATT_STAGE + 32768, gVh, 0, tid);
    cp_commit();

    cp_wait1();            // Q ready
    __syncthreads();

    uint32_t qh_f[8][4];
    {
        int r = wid * 16 + (lane & 15);
#pragma unroll
        for (int kf = 0; kf < 8; kf++) {
            int c = 2 * kf + (lane >> 4);
            ldm_x4(qh_f[kf], sw_addr(sb, r, c));
        }
    }
    __syncthreads();       // Q region (buf0) reusable

    // tile 1 -> buf0
    att_load_tile(sb + 0,     gKh, ATT_BK, tid);
    att_load_tile(sb + 32768, gVh, ATT_BK, tid);
    cp_commit();

    float mA = -INFINITY, mB = -INFINITY, lA = 0.f, lB = 0.f;
    float ctx[16][4];
#pragma unroll
    for (int i = 0; i < 16; i++)
#pragma unroll
        for (int j = 0; j < 4; j++) ctx[i][j] = 0.f;

    const float SCALE = 0.088388347648318447f;
    const float LOG2E = 1.4426950408889634f;
    const int rA = q0 + wid * 16 + (lane >> 2);
    const int rB = rA + 8;
    const int cb = 2 * (lane & 3);

    const int s_br = (lane & 7) + ((lane >> 4) & 1) * 8;
    const int s_bc = (lane >> 3) & 1;
    const int a_r = (lane & 15);
    const int a_c = (lane >> 4);

    for (int kt = 0; kt < ATT_NT; kt++) {
        if (kt < ATT_NT - 2) cp_wait1(); else cp_wait0();
        __syncthreads();
        // tile kt lives in buffer (kt+1)&1
        const uint32_t buf = sb + (uint32_t)((kt + 1) & 1) * ATT_STAGE;
        const int k0 = kt * ATT_BK;

        // ---- S = scale * Qh @ Kh^T + bias over 128 keys (16 n-tiles)
        float sacc[16][4];
#pragma unroll
        for (int i = 0; i < 16; i++)
#pragma unroll
            for (int j = 0; j < 4; j++) sacc[i][j] = 0.f;

#pragma unroll
        for (int kf = 0; kf < 8; kf++) {
#pragma unroll
            for (int ng = 0; ng < 8; ng++) {
                int r = ng * 16 + s_br;
                int c = 2 * kf + s_bc;
                uint32_t th[4];
                ldm_x4(th, sw_addr(buf, r, c));
                uint32_t b0[2] = {th[0], th[1]}, b1[2] = {th[2], th[3]};
                mma_f16(sacc[2 * ng],     qh_f[kf], b0);
                mma_f16(sacc[2 * ng + 1], qh_f[kf], b1);
            }
        }

        // ---- bias + max
        float mxA = -INFINITY, mxB = -INFINITY;
#pragma unroll
        for (int nt = 0; nt < 16; nt++) {
            float2 bA = *(const float2*)(biasM + (size_t)rA * L_SEQ + k0 + nt * 8 + cb);
            float2 bB = *(const float2*)(biasM + (size_t)rB * L_SEQ + k0 + nt * 8 + cb);
            sacc[nt][0] = fmaf(sacc[nt][0], SCALE, bA.x);
            sacc[nt][1] = fmaf(sacc[nt][1], SCALE, bA.y);
            sacc[nt][2] = fmaf(sacc[nt][2], SCALE, bB.x);
            sacc[nt][3] = fmaf(sacc[nt][3], SCALE, bB.y);
            mxA = fmaxf(mxA, fmaxf(sacc[nt][0], sacc[nt][1]));
            mxB = fmaxf(mxB, fmaxf(sacc[nt][2], sacc[nt][3]));
        }
        mxA = fmaxf(mxA, __shfl_xor_sync(0xffffffffu, mxA, 1));
        mxA = fmaxf(mxA, __shfl_xor_sync(0xffffffffu, mxA, 2));
        mxB = fmaxf(mxB, __shfl_xor_sync(0xffffffffu, mxB, 1));
        mxB = fmaxf(mxB, __shfl_xor_sync(0xffffffffu, mxB, 2));
        float mnA = fmaxf(mA, mxA), mnB = fmaxf(mB, mxB);
        float alA = ex2((mA - mnA) * LOG2E);
        float alB = ex2((mB - mnB) * LOG2E);
        float negA = mnA * LOG2E, negB = mnB * LOG2E;
        float sumA = 0.f, sumB = 0.f;
#pragma unroll
        for (int nt = 0; nt < 16; nt++) {
            sacc[nt][0] = ex2(fmaf(sacc[nt][0], LOG2E, -negA));
            sacc[nt][1] = ex2(fmaf(sacc[nt][1], LOG2E, -negA));
            sacc[nt][2] = ex2(fmaf(sacc[nt][2], LOG2E, -negB));
            sacc[nt][3] = ex2(fmaf(sacc[nt][3], LOG2E, -negB));
            sumA += sacc[nt][0] + sacc[nt][1];
            sumB += sacc[nt][2] + sacc[nt][3];
        }
        sumA += __shfl_xor_sync(0xffffffffu, sumA, 1);
        sumA += __shfl_xor_sync(0xffffffffu, sumA, 2);
        sumB += __shfl_xor_sync(0xffffffffu, sumB, 1);
        sumB += __shfl_xor_sync(0xffffffffu, sumB, 2);
        lA = lA * alA + sumA;
        lB = lB * alB + sumB;
        mA = mnA; mB = mnB;
#pragma unroll
        for (int nt = 0; nt < 16; nt++) {
            ctx[nt][0] *= alA; ctx[nt][1] *= alA;
            ctx[nt][2] *= alB; ctx[nt][3] *= alB;
        }

        // ---- P fragments (8 k-blocks of 16 keys)
        uint32_t pah[8][4];
#pragma unroll
        for (int kb = 0; kb < 8; kb++) {
#pragma unroll
            for (int half = 0; half < 2; half++) {
#pragma unroll
                for (int sub = 0; sub < 2; sub++) {
                    float p0 = sacc[2 * kb + sub][2 * half + 0];
                    float p1 = sacc[2 * kb + sub][2 * half + 1];
                    pah[kb][sub * 2 + half] =
                        pack_h2(__float2half_rn(p0), __float2half_rn(p1));
                }
            }
        }

        // ---- ctx += Ph @ Vh over 128 keys, V via ldmatrix.trans
#pragma unroll
        for (int kb = 0; kb < 8; kb++) {
#pragma unroll
            for (int db = 0; db < 8; db++) {
                int r = kb * 16 + a_r;
                int c = 2 * db + a_c;
                uint32_t th[4];
                ldm_x4_t(th, sw_addr(buf + 32768, r, c));
                uint32_t b0[2] = {th[0], th[1]}, b1[2] = {th[2], th[3]};
                mma_f16(ctx[2 * db],     pah[kb], b0);
                mma_f16(ctx[2 * db + 1], pah[kb], b1);
            }
        }

        __syncthreads();
        if (kt + 2 < ATT_NT) {
            const uint32_t nbuf = sb + (uint32_t)((kt + 1) & 1) * ATT_STAGE;
            const int nk0 = (kt + 2) * ATT_BK;
            att_load_tile(nbuf + 0,     gKh, nk0, tid);
            att_load_tile(nbuf + 32768, gVh, nk0, tid);
            cp_commit();
        } else {
            cp_commit();
        }
    }

    // ---- epilogue: normalize, round to fp16, write ctx
    float iA = 1.f / lA, iB = 1.f / lB;
#pragma unroll
    for (int nt = 0; nt < 16; nt++) {
        int col = h * D_HEAD + nt * 8 + cb;
        float v0 = ctx[nt][0] * iA, v1 = ctx[nt][1] * iA;
        float v2 = ctx[nt][2] * iB, v3 = ctx[nt][3] * iB;
        *(uint32_t*)(ch + (size_t)rA * E_DIM + col) =
            pack_h2(__float2half_rn(v0), __float2half_rn(v1));
        *(uint32_t*)(ch + (size_t)rB * E_DIM + col) =
            pack_h2(__float2half_rn(v2), __float2half_rn(v3));
    }
}

// ---------------------------------------------------------------------------
extern "C" void kernel_launch(void* const* d_in, const int* in_sizes, int n_in,
                              void* d_out, int out_size)
{
    const float* x     = (const float*)d_in[0];
    const float* biasM = (const float*)d_in[1];
    const float* w_in  = (const float*)d_in[2];
    const float* b_in  = (const float*)d_in[3];
    const float* w_out = (const float*)d_in[4];
    const float* b_out = (const float*)d_in[5];
    float* out = (float*)d_out;

    __half *xh, *wih, *woh, *qkvh, *ch;
    cudaGetSymbolAddress((void**)&xh, g_xh);
    cudaGetSymbolAddress((void**)&wih, g_wih);
    cudaGetSymbolAddress((void**)&woh, g_woh);
    cudaGetSymbolAddress((void**)&qkvh, g_qkvh);
    cudaGetSymbolAddress((void**)&ch, g_ch);

    cudaFuncSetAttribute(gemm_mma, cudaFuncAttributeMaxDynamicSharedMemorySize, GM_SMEM);
    cudaFuncSetAttribute(attn_tc, cudaFuncAttributeMaxDynamicSharedMemorySize, ATT_SMEM);

    {
        int n4 = (L_SEQ * E_DIM) / 4;
        conv_f16_kernel<<<(n4 + 255) / 256, 256>>>(x, xh, n4);
        int w4 = (E3 * E_DIM) / 4;
        conv_f16_kernel<<<(w4 + 255) / 256, 256>>>(w_in, wih, w4);
        int o4 = (E_DIM * E_DIM) / 4;
        conv_f16_kernel<<<(o4 + 255) / 256, 256>>>(w_out, woh, o4);
    }

    // 1) QKV projection -> fp16   [2048, 6144]
    gemm_mma<<<dim3(E3 / 128, L_SEQ / 128), 256, GM_SMEM>>>(
        xh, wih, b_in, nullptr, qkvh, L_SEQ, E3, E_DIM);

    // 2) fp16 flash attention (BK=128) -> fp16 ctx
    attn_tc<<<dim3(L_SEQ / 128, H_NUM), 256, ATT_SMEM>>>(
        qkvh, biasM, ch);

    // 3) out projection -> fp32 output   [2048, 2048]
    gemm_mma<<<dim3(E_DIM / 128, L_SEQ / 128), 256, GM_SMEM>>>(
        ch, woh, b_out, out, nullptr, L_SEQ, E_DIM, E_DIM);
}